// round 13
// baseline (speedup 1.0000x reference)
#include <cuda_runtime.h>
#include <cuda_fp16.h>
#include <math.h>

#define NTOT   50000
#define NTYPE0 30000
#define ETOT   400000
#define NPAD   50048

// ---------------- static scratch ----------------
__device__ float  g_h[NPAD * 256];
__device__ float  g_acc[NPAD * 256];
__device__ __half g_feat16[2 * NPAD * 256];
__device__ float  g_l2out[NPAD * 64];
__device__ float  g_w2pack[256 * 64];
__device__ float  g_el[2][NTOT * 4];
__device__ float  g_er[2][NTOT * 4];
__device__ float  g_den[2][NTOT * 4];
__device__ float  g_alpha[2][ETOT * 4];
__device__ int    g_rowptr[2][NTOT + 1];
__device__ int    g_cursor[2][NTOT];
__device__ int    g_counts[2][NTOT];
__device__ int    g_csrsrc[2][ETOT];

// ---------------- packed f32x2 helpers (FFMA2: 2x fp32 FMA rate on sm_103a) --------
__device__ __forceinline__ unsigned long long pack2(float x, float y) {
    unsigned long long r;
    asm("mov.b64 %0, {%1, %2};" : "=l"(r) : "f"(x), "f"(y));
    return r;
}
__device__ __forceinline__ void ffma2(unsigned long long& d, unsigned long long a,
                                      unsigned long long b) {
    asm("fma.rn.f32x2 %0, %1, %2, %3;" : "=l"(d) : "l"(a), "l"(b), "l"(d));
}
__device__ __forceinline__ float2 unpack2(unsigned long long v) {
    float2 r;
    asm("mov.b64 {%0, %1}, %2;" : "=f"(r.x), "=f"(r.y) : "l"(v));
    return r;
}

// ---------------- CSR build ----------------
__global__ void zero2_k(int* __restrict__ c)
{
    int t = blockIdx.x * blockDim.x + threadIdx.x;
    if (t < 2 * NTOT) c[t] = 0;
}

__global__ void count_k(const int* __restrict__ dst, int* __restrict__ counts)
{
    int e = blockIdx.x * blockDim.x + threadIdx.x;
    if (e < ETOT) atomicAdd(&counts[dst[e]], 1);
}

__global__ void scan_k(const int* __restrict__ counts, int* __restrict__ rowptr,
                       int* __restrict__ cursor)
{
    __shared__ int warp_sums[32];
    __shared__ int s_carry;
    int tid = threadIdx.x, lane = tid & 31, wid = tid >> 5;
    int nw = blockDim.x >> 5;
    if (tid == 0) s_carry = 0;
    __syncthreads();
    for (int base = 0; base < NTOT; base += blockDim.x) {
        int i = base + tid;
        int v = (i < NTOT) ? counts[i] : 0;
        int x = v;
#pragma unroll
        for (int o = 1; o < 32; o <<= 1) {
            int y = __shfl_up_sync(~0u, x, o);
            if (lane >= o) x += y;
        }
        if (lane == 31) warp_sums[wid] = x;
        __syncthreads();
        if (wid == 0) {
            int s = (lane < nw) ? warp_sums[lane] : 0;
#pragma unroll
            for (int o = 1; o < 32; o <<= 1) {
                int y = __shfl_up_sync(~0u, s, o);
                if (lane >= o) s += y;
            }
            warp_sums[lane] = s;
        }
        __syncthreads();
        int woff = (wid == 0) ? 0 : warp_sums[wid - 1];
        int incl = x + woff;
        int excl = incl - v;
        int carry = s_carry;
        if (i < NTOT) { rowptr[i] = carry + excl; cursor[i] = carry + excl; }
        __syncthreads();
        if (tid == blockDim.x - 1) s_carry = carry + incl;
        __syncthreads();
    }
    if (tid == 0) rowptr[NTOT] = s_carry;
}

__global__ void scatter_k(const int* __restrict__ src, const int* __restrict__ dst,
                          int* __restrict__ cursor, int* __restrict__ csrsrc)
{
    int e = blockIdx.x * blockDim.x + threadIdx.x;
    if (e >= ETOT) return;
    int pos = atomicAdd(&cursor[dst[e]], 1);
    csrsrc[pos] = src[e];
}

// ---------------- 64x64 tile fp32 GEMM with FFMA2 (small-N cases) ----------------
__global__ void gemm64(const float* __restrict__ A, const float* __restrict__ B,
                       const float* __restrict__ bias, float* __restrict__ C,
                       int M, int K, int N)
{
    __shared__ float As[16][65];
    __shared__ float Bs[16][64];
    int tid = threadIdx.x;
    int rowBase = blockIdx.y * 64;
    int colBase = blockIdx.x * 64;
    int tx = tid & 15, ty = tid >> 4;
    int arow = tid >> 2, acol = (tid & 3) << 2;
    int brow = tid >> 4, bcol = (tid & 15) << 2;

    unsigned long long acc[4][2];
#pragma unroll
    for (int i = 0; i < 4; i++) { acc[i][0] = 0ull; acc[i][1] = 0ull; }

    for (int k0 = 0; k0 < K; k0 += 16) {
        float4 av = make_float4(0.f, 0.f, 0.f, 0.f);
        if (rowBase + arow < M)
            av = *reinterpret_cast<const float4*>(A + (size_t)(rowBase + arow) * K + k0 + acol);
        As[acol + 0][arow] = av.x; As[acol + 1][arow] = av.y;
        As[acol + 2][arow] = av.z; As[acol + 3][arow] = av.w;
        float4 bv = make_float4(0.f, 0.f, 0.f, 0.f);
        if (colBase + bcol < N)
            bv = *reinterpret_cast<const float4*>(B + (size_t)(k0 + brow) * N + colBase + bcol);
        *reinterpret_cast<float4*>(&Bs[brow][bcol]) = bv;
        __syncthreads();
#pragma unroll
        for (int k = 0; k < 16; k++) {
            float a0 = As[k][(ty << 2) + 0], a1 = As[k][(ty << 2) + 1];
            float a2 = As[k][(ty << 2) + 2], a3 = As[k][(ty << 2) + 3];
            unsigned long long b01 = *reinterpret_cast<const unsigned long long*>(&Bs[k][(tx << 2) + 0]);
            unsigned long long b23 = *reinterpret_cast<const unsigned long long*>(&Bs[k][(tx << 2) + 2]);
            unsigned long long p0 = pack2(a0, a0), p1 = pack2(a1, a1);
            unsigned long long p2 = pack2(a2, a2), p3 = pack2(a3, a3);
            ffma2(acc[0][0], p0, b01); ffma2(acc[0][1], p0, b23);
            ffma2(acc[1][0], p1, b01); ffma2(acc[1][1], p1, b23);
            ffma2(acc[2][0], p2, b01); ffma2(acc[2][1], p2, b23);
            ffma2(acc[3][0], p3, b01); ffma2(acc[3][1], p3, b23);
        }
        __syncthreads();
    }
#pragma unroll
    for (int i = 0; i < 4; i++) {
        int r = rowBase + (ty << 2) + i;
        if (r >= M) continue;
        float2 u0 = unpack2(acc[i][0]);
        float2 u1 = unpack2(acc[i][1]);
        float vals[4] = {u0.x, u0.y, u1.x, u1.y};
#pragma unroll
        for (int j = 0; j < 4; j++) {
            int c = colBase + (tx << 2) + j;
            if (c < N) C[(size_t)r * N + c] = vals[j] + (bias ? bias[c] : 0.f);
        }
    }
}

// ---------------- 128x128 tile fp32 GEMM (R4 shape) + fused scores + fp16 output ---
// N == 256. Block (ct=blockIdx.x) owns heads {2ct, 2ct+1}; el/er computed from the
// fp32 accumulators via 16-lane shfl reduce. feat written as fp16.
__global__ void __launch_bounds__(256, 2)
gemm128s(const float* __restrict__ A, const float* __restrict__ B,
         __half* __restrict__ C16, int M, int K, int N,
         long long bStride, long long cStride,
         const float* __restrict__ al, const float* __restrict__ ar,
         float* __restrict__ elb, float* __restrict__ erb)
{
    __shared__ float As[8][132];
    __shared__ float Bs[8][128];
    const float* Bp = B + (long long)blockIdx.z * bStride;
    __half* Cp = C16 + (long long)blockIdx.z * cStride;

    int tid = threadIdx.x;
    int rb = blockIdx.y * 128, cb = blockIdx.x * 128;
    int tx = tid & 15, ty = tid >> 4;
    int arow = tid >> 1, acol = (tid & 1) << 2;
    int brow = tid >> 5, bcol = (tid & 31) << 2;

    unsigned long long acc[8][4];
#pragma unroll
    for (int i = 0; i < 8; i++)
#pragma unroll
        for (int j = 0; j < 4; j++) acc[i][j] = 0ull;

    for (int k0 = 0; k0 < K; k0 += 8) {
        float4 av = make_float4(0.f, 0.f, 0.f, 0.f);
        if (rb + arow < M)
            av = *reinterpret_cast<const float4*>(A + (size_t)(rb + arow) * K + k0 + acol);
        As[acol + 0][arow] = av.x; As[acol + 1][arow] = av.y;
        As[acol + 2][arow] = av.z; As[acol + 3][arow] = av.w;
        float4 bv = *reinterpret_cast<const float4*>(Bp + (size_t)(k0 + brow) * N + cb + bcol);
        *reinterpret_cast<float4*>(&Bs[brow][bcol]) = bv;
        __syncthreads();
#pragma unroll
        for (int k = 0; k < 8; k++) {
            float a[8];
            *reinterpret_cast<float4*>(a)     = *reinterpret_cast<float4*>(&As[k][ty * 8]);
            *reinterpret_cast<float4*>(a + 4) = *reinterpret_cast<float4*>(&As[k][ty * 8 + 4]);
            unsigned long long b2[4];
            b2[0] = *reinterpret_cast<const unsigned long long*>(&Bs[k][tx * 4]);
            b2[1] = *reinterpret_cast<const unsigned long long*>(&Bs[k][tx * 4 + 2]);
            b2[2] = *reinterpret_cast<const unsigned long long*>(&Bs[k][64 + tx * 4]);
            b2[3] = *reinterpret_cast<const unsigned long long*>(&Bs[k][64 + tx * 4 + 2]);
#pragma unroll
            for (int i = 0; i < 8; i++) {
                unsigned long long aa = pack2(a[i], a[i]);
                ffma2(acc[i][0], aa, b2[0]);
                ffma2(acc[i][1], aa, b2[1]);
                ffma2(acc[i][2], aa, b2[2]);
                ffma2(acc[i][3], aa, b2[3]);
            }
        }
        __syncthreads();
    }

    // attention vectors for this block's two heads
    const float* alg = al + (size_t)blockIdx.z * 256;
    const float* arg = ar + (size_t)blockIdx.z * 256;
    float* elg = elb + (size_t)blockIdx.z * (NTOT * 4);
    float* erg = erb + (size_t)blockIdx.z * (NTOT * 4);
    int hbase = cb >> 6;
    float alv0[4], arv0[4], alv1[4], arv1[4];
#pragma unroll
    for (int j = 0; j < 4; j++) {
        alv0[j] = alg[cb + tx * 4 + j];       arv0[j] = arg[cb + tx * 4 + j];
        alv1[j] = alg[cb + 64 + tx * 4 + j];  arv1[j] = arg[cb + 64 + tx * 4 + j];
    }

#pragma unroll
    for (int i = 0; i < 8; i++) {
        int r = rb + ty * 8 + i;
        float2 u0 = unpack2(acc[i][0]), u1 = unpack2(acc[i][1]);
        float2 u2 = unpack2(acc[i][2]), u3 = unpack2(acc[i][3]);
        float v[8] = {u0.x, u0.y, u1.x, u1.y, u2.x, u2.y, u3.x, u3.y};

        // fp16 stores (4 halves = 8B per segment)
        __half2 h0 = __floats2half2_rn(v[0], v[1]);
        __half2 h1 = __floats2half2_rn(v[2], v[3]);
        __half2 h2 = __floats2half2_rn(v[4], v[5]);
        __half2 h3 = __floats2half2_rn(v[6], v[7]);
        __half* cp0 = Cp + (size_t)r * 256 + cb + tx * 4;
        __half* cp1 = Cp + (size_t)r * 256 + cb + 64 + tx * 4;
        *reinterpret_cast<__half2*>(cp0)     = h0;
        *reinterpret_cast<__half2*>(cp0 + 2) = h1;
        *reinterpret_cast<__half2*>(cp1)     = h2;
        *reinterpret_cast<__half2*>(cp1 + 2) = h3;

        // fused attention scores from fp32 accumulators
        float se0 = 0.f, sr0 = 0.f, se1 = 0.f, sr1 = 0.f;
#pragma unroll
        for (int j = 0; j < 4; j++) {
            se0 += v[j] * alv0[j];     sr0 += v[j] * arv0[j];
            se1 += v[4 + j] * alv1[j]; sr1 += v[4 + j] * arv1[j];
        }
#pragma unroll
        for (int o = 8; o > 0; o >>= 1) {
            se0 += __shfl_down_sync(~0u, se0, o, 16);
            sr0 += __shfl_down_sync(~0u, sr0, o, 16);
            se1 += __shfl_down_sync(~0u, se1, o, 16);
            sr1 += __shfl_down_sync(~0u, sr1, o, 16);
        }
        if (tx == 0 && r < NTOT) {
            elg[r * 4 + hbase]     = se0;
            erg[r * 4 + hbase]     = sr0;
            elg[r * 4 + hbase + 1] = se1;
            erg[r * 4 + hbase + 1] = sr1;
        }
    }
}

// ---------------- pack layer-2 weights: cols = [W2g0 | W2g1 | res2g0 | res2g1] ------
__global__ void pack_w2_k(const float* __restrict__ W2, const float* __restrict__ res2,
                          float* __restrict__ out)
{
    int idx = blockIdx.x * blockDim.x + threadIdx.x;
    if (idx >= 256 * 64) return;
    int k = idx >> 6, d = idx & 63;
    int g = (d >> 4) & 1;
    int which = d >> 5;
    int dd = d & 15;
    const float* src = which == 0 ? W2 : res2;
    out[idx] = src[(size_t)g * 256 * 16 + k * 16 + dd];
}

// ---------------- attention scores (layer 2 only): warp per (node, head) -----------
__global__ void scores_k(const float* __restrict__ feat, int stride,
                         const float* __restrict__ al, const float* __restrict__ ar,
                         float* __restrict__ el, float* __restrict__ er, int H, int D)
{
    int n = blockIdx.x;
    int wid = threadIdx.x >> 5;
    int lane = threadIdx.x & 31;
    const float* f = feat + (size_t)n * stride + wid * D;
    float sl = 0.f, sr = 0.f;
    for (int d = lane; d < D; d += 32) {
        float v = f[d];
        sl += v * al[wid * D + d];
        sr += v * ar[wid * D + d];
    }
#pragma unroll
    for (int o = 16; o > 0; o >>= 1) {
        sl += __shfl_down_sync(~0u, sl, o);
        sr += __shfl_down_sync(~0u, sr, o);
    }
    if (lane == 0) { el[n * H + wid] = sl; er[n * H + wid] = sr; }
}

// ---------------- SINGLE-PASS edge softmax (CSR, warp per dst node) ----------------
// Scores are tiny so exp without max-shift is safe. alpha holds unnormalized exp;
// invden applied once in the aggregation epilogue.
template <int H>
__global__ void softmax_k(const int* __restrict__ rowptr, const int* __restrict__ csrsrc,
                          const float* __restrict__ el, const float* __restrict__ er,
                          float* __restrict__ alpha, float* __restrict__ invden)
{
    int n = blockIdx.x * (blockDim.x >> 5) + (threadIdx.x >> 5);
    int lane = threadIdx.x & 31;
    if (n >= NTOT) return;
    int beg = rowptr[n], end = rowptr[n + 1];
    if (beg == end) return;

    float erh[H];
#pragma unroll
    for (int h = 0; h < H; h++) erh[h] = er[n * H + h];

    float den[H];
#pragma unroll
    for (int h = 0; h < H; h++) den[h] = 0.f;

    for (int p = beg + lane; p < end; p += 32) {
        int s = csrsrc[p];
#pragma unroll
        for (int h = 0; h < H; h++) {
            float e = el[s * H + h] + erh[h];
            e = e > 0.f ? e : 0.2f * e;
            float x = expf(e);
            alpha[p * H + h] = x;
            den[h] += x;
        }
    }
#pragma unroll
    for (int h = 0; h < H; h++)
#pragma unroll
        for (int o = 16; o > 0; o >>= 1)
            den[h] += __shfl_xor_sync(~0u, den[h], o);

    if (lane == 0) {
#pragma unroll
        for (int h = 0; h < H; h++)
            invden[n * H + h] = 1.f / den[h];
    }
}

// ---------------- fused dual-graph aggregation + epilogue (HD=256, fp16 feat) ------
__global__ void aggr256_k(const int* __restrict__ rp0, const int* __restrict__ cs0,
                          const float* __restrict__ a0, const float* __restrict__ dn0,
                          const __half* __restrict__ f0,
                          const int* __restrict__ rp1, const int* __restrict__ cs1,
                          const float* __restrict__ a1, const float* __restrict__ dn1,
                          const __half* __restrict__ f1,
                          const float* __restrict__ h, const float* __restrict__ bias0,
                          const float* __restrict__ bias1, const float* __restrict__ mixw,
                          int layer, int useRes, float* __restrict__ out)
{
    int n = blockIdx.x;
    int d = threadIdx.x;
    int head = d >> 6;

    float acc0 = 0.f, acc1 = 0.f;
    {
        int p = rp0[n], e = rp0[n + 1];
        for (; p + 2 <= e; p += 2) {
            int s0 = __ldg(&cs0[p]),     s1 = __ldg(&cs0[p + 1]);
            float w0 = __ldg(&a0[p * 4 + head]);
            float w1 = __ldg(&a0[(p + 1) * 4 + head]);
            float v0 = __half2float(f0[(size_t)s0 * 256 + d]);
            float v1 = __half2float(f0[(size_t)s1 * 256 + d]);
            acc0 += v0 * w0 + v1 * w1;
        }
        if (p < e) {
            int s = __ldg(&cs0[p]);
            acc0 += __half2float(f0[(size_t)s * 256 + d]) * __ldg(&a0[p * 4 + head]);
        }
    }
    {
        int p = rp1[n], e = rp1[n + 1];
        for (; p + 2 <= e; p += 2) {
            int s0 = __ldg(&cs1[p]),     s1 = __ldg(&cs1[p + 1]);
            float w0 = __ldg(&a1[p * 4 + head]);
            float w1 = __ldg(&a1[(p + 1) * 4 + head]);
            float v0 = __half2float(f1[(size_t)s0 * 256 + d]);
            float v1 = __half2float(f1[(size_t)s1 * 256 + d]);
            acc1 += v0 * w0 + v1 * w1;
        }
        if (p < e) {
            int s = __ldg(&cs1[p]);
            acc1 += __half2float(f1[(size_t)s * 256 + d]) * __ldg(&a1[p * 4 + head]);
        }
    }

    acc0 *= __ldg(&dn0[n * 4 + head]);
    acc1 *= __ldg(&dn1[n * 4 + head]);

    float res = useRes ? h[(size_t)n * 256 + d] : 0.f;
    float v0 = acc0 + res + bias0[d];
    float v1 = acc1 + res + bias1[d];
    v0 = v0 > 0.f ? v0 : expm1f(v0);
    v1 = v1 > 0.f ? v1 : expm1f(v1);

    int ty = (n < NTYPE0) ? 0 : 1;
    float m0 = mixw[ty * 6 + layer * 2 + 0];
    float m1 = mixw[ty * 6 + layer * 2 + 1];
    float mxw = fmaxf(m0, m1);
    float e0 = expf(m0 - mxw), e1 = expf(m1 - mxw);
    float inv = 1.f / (e0 + e1);
    out[(size_t)n * 256 + d] = v0 * (e0 * inv) + v1 * (e1 * inv);
}

// ---------------- layer 2 aggregation (H=1, D=16), packed fp32 l2 buffer -----------
__global__ void aggr16_k(const int* __restrict__ rp0, const int* __restrict__ cs0,
                         const float* __restrict__ a0, const float* __restrict__ dn0,
                         const int* __restrict__ rp1, const int* __restrict__ cs1,
                         const float* __restrict__ a1, const float* __restrict__ dn1,
                         const float* __restrict__ l2, const float* __restrict__ b2,
                         const float* __restrict__ mixw, float* __restrict__ logits)
{
    int n = blockIdx.x * 16 + (threadIdx.x >> 4);
    int d = threadIdx.x & 15;
    if (n >= NTOT) return;

    float acc0 = 0.f, acc1 = 0.f;
    int b = rp0[n], e = rp0[n + 1];
    for (int p = b; p < e; p++)
        acc0 += l2[(size_t)__ldg(&cs0[p]) * 64 + d] * __ldg(&a0[p]);
    b = rp1[n]; e = rp1[n + 1];
    for (int p = b; p < e; p++)
        acc1 += l2[(size_t)__ldg(&cs1[p]) * 64 + 16 + d] * __ldg(&a1[p]);

    acc0 *= __ldg(&dn0[n]);
    acc1 *= __ldg(&dn1[n]);

    float v0 = acc0 + l2[(size_t)n * 64 + 32 + d] + b2[d];
    float v1 = acc1 + l2[(size_t)n * 64 + 48 + d] + b2[16 + d];

    int ty = (n < NTYPE0) ? 0 : 1;
    float m0 = mixw[ty * 6 + 4 + 0];
    float m1 = mixw[ty * 6 + 4 + 1];
    float mxw = fmaxf(m0, m1);
    float e0 = expf(m0 - mxw), e1 = expf(m1 - mxw);
    float inv = 1.f / (e0 + e1);
    logits[(size_t)n * 16 + d] = v0 * (e0 * inv) + v1 * (e1 * inv);
}

// ---------------- host orchestration ----------------
extern "C" void kernel_launch(void* const* d_in, const int* in_sizes, int n_in,
                              void* d_out, int out_size)
{
    const float* features0 = (const float*)d_in[0];
    const float* features1 = (const float*)d_in[1];
    const float* fc_w0 = (const float*)d_in[2];
    const float* fc_b0 = (const float*)d_in[3];
    const float* fc_w1 = (const float*)d_in[4];
    const float* fc_b1 = (const float*)d_in[5];
    const float* mix_w = (const float*)d_in[6];
    const float* W0  = (const float*)d_in[7];
    const float* al0 = (const float*)d_in[8];
    const float* ar0 = (const float*)d_in[9];
    const float* b0  = (const float*)d_in[10];
    const float* W1  = (const float*)d_in[11];
    const float* al1 = (const float*)d_in[12];
    const float* ar1 = (const float*)d_in[13];
    const float* b1  = (const float*)d_in[14];
    const float* W2  = (const float*)d_in[15];
    const float* al2 = (const float*)d_in[16];
    const float* ar2 = (const float*)d_in[17];
    const float* b2  = (const float*)d_in[18];
    const float* res2= (const float*)d_in[19];
    const int* srcs[2] = {(const int*)d_in[20], (const int*)d_in[22]};
    const int* dsts[2] = {(const int*)d_in[21], (const int*)d_in[23]};

    float *h, *acc, *l2out, *w2pack, *elp, *erp, *denp, *alphap;
    __half* feat16b;
    int *rowptrp, *cursorp, *countsp, *csrsrcp;
    cudaGetSymbolAddress((void**)&h,       g_h);
    cudaGetSymbolAddress((void**)&acc,     g_acc);
    cudaGetSymbolAddress((void**)&feat16b, g_feat16);
    cudaGetSymbolAddress((void**)&l2out,   g_l2out);
    cudaGetSymbolAddress((void**)&w2pack,  g_w2pack);
    cudaGetSymbolAddress((void**)&elp,     g_el);
    cudaGetSymbolAddress((void**)&erp,     g_er);
    cudaGetSymbolAddress((void**)&denp,    g_den);
    cudaGetSymbolAddress((void**)&alphap,  g_alpha);
    cudaGetSymbolAddress((void**)&rowptrp, g_rowptr);
    cudaGetSymbolAddress((void**)&cursorp, g_cursor);
    cudaGetSymbolAddress((void**)&countsp, g_counts);
    cudaGetSymbolAddress((void**)&csrsrcp, g_csrsrc);

    __half* feat16[2] = {feat16b, feat16b + (size_t)NPAD * 256};
    float* el[2]    = {elp, elp + NTOT * 4};
    float* er[2]    = {erp, erp + NTOT * 4};
    float* den[2]   = {denp, denp + NTOT * 4};
    float* alpha[2] = {alphap, alphap + ETOT * 4};
    int* rowptr[2]  = {rowptrp, rowptrp + NTOT + 1};
    int* cursor[2]  = {cursorp, cursorp + NTOT};
    int* counts[2]  = {countsp, countsp + NTOT};
    int* csrsrc[2]  = {csrsrcp, csrsrcp + ETOT};

    const int TPB = 256;
    const int N1n = NTOT - NTYPE0;
    const int EB = (ETOT + TPB - 1) / TPB;
    const int MB = (NTOT + 127) / 128;

    // 1-3: setup; 4: gemm128s (ncu captures this launch)
    zero2_k<<<(2 * NTOT + TPB - 1) / TPB, TPB>>>(countsp);                        // 1
    gemm64<<<dim3(1, (NTYPE0 + 63) / 64), TPB>>>(features0, fc_w0, fc_b0, h,
                                                 NTYPE0, 128, 64);                // 2
    gemm64<<<dim3(1, (N1n + 63) / 64), TPB>>>(features1, fc_w1, fc_b1,
                                              h + (size_t)NTYPE0 * 64,
                                              N1n, 128, 64);                      // 3
    gemm128s<<<dim3(2, MB, 2), 256>>>(h, W0, feat16b, NTOT, 64, 256,
                                      (long long)64 * 256, (long long)NPAD * 256,
                                      al0, ar0, elp, erp);                        // 4 <- profiled

    // CSR builds
    count_k<<<EB, TPB>>>(dsts[0], counts[0]);
    count_k<<<EB, TPB>>>(dsts[1], counts[1]);
    scan_k<<<1, 1024>>>(counts[0], rowptr[0], cursor[0]);
    scan_k<<<1, 1024>>>(counts[1], rowptr[1], cursor[1]);
    scatter_k<<<EB, TPB>>>(srcs[0], dsts[0], cursor[0], csrsrc[0]);
    scatter_k<<<EB, TPB>>>(srcs[1], dsts[1], cursor[1], csrsrc[1]);
    pack_w2_k<<<64, 256>>>(W2, res2, w2pack);

    float* cur = h;
    float* nxt = acc;
    for (int l = 0; l < 2; l++) {
        const float* bl = (l == 0) ? b0 : b1;
        if (l != 0)
            gemm128s<<<dim3(2, MB, 2), 256>>>(cur, W1, feat16b, NTOT, 256, 256,
                                              (long long)256 * 256, (long long)NPAD * 256,
                                              al1, ar1, elp, erp);
        for (int gi = 0; gi < 2; gi++)
            softmax_k<4><<<(NTOT + 7) / 8, 256>>>(rowptr[gi], csrsrc[gi], el[gi], er[gi],
                                                  alpha[gi], den[gi]);
        aggr256_k<<<NTOT, 256>>>(rowptr[0], csrsrc[0], alpha[0], den[0], feat16[0],
                                 rowptr[1], csrsrc[1], alpha[1], den[1], feat16[1],
                                 cur, bl, bl + 256, mix_w, l, (l == 1) ? 1 : 0, nxt);
        float* t = cur; cur = nxt; nxt = t;
    }

    // ---- layer 2 (H=1, D=16): single packed N=64 GEMM, softmax, aggregate ----
    gemm64<<<dim3(1, (NTOT + 63) / 64), TPB>>>(cur, w2pack, nullptr, l2out, NTOT, 256, 64);
    for (int gi = 0; gi < 2; gi++) {
        scores_k<<<NTOT, 32>>>(l2out + gi * 16, 64, al2 + gi * 16, ar2 + gi * 16,
                               el[gi], er[gi], 1, 16);
        softmax_k<1><<<(NTOT + 7) / 8, 256>>>(rowptr[gi], csrsrc[gi], el[gi], er[gi],
                                              alpha[gi], den[gi]);
    }
    aggr16_k<<<(NTOT + 15) / 16, 256>>>(rowptr[0], csrsrc[0], alpha[0], den[0],
                                        rowptr[1], csrsrc[1], alpha[1], den[1],
                                        l2out, b2, mix_w, (float*)d_out);
}

// round 14
// speedup vs baseline: 1.3007x; 1.3007x over previous
#include <cuda_runtime.h>
#include <math.h>

#define NTOT   50000
#define NTYPE0 30000
#define ETOT   400000
#define NPAD   50048

// ---------------- static scratch ----------------
__device__ float g_h[NPAD * 256];
__device__ float g_acc[NPAD * 256];
__device__ float g_feat[2 * NPAD * 256];
__device__ float g_l2out[NPAD * 64];
__device__ float g_w2pack[256 * 64];
__device__ float g_el[2][NTOT * 4];
__device__ float g_er[2][NTOT * 4];
__device__ float g_alpha[2][ETOT * 4];
__device__ int   g_rowptr[2][NTOT + 1];
__device__ int   g_cursor[2][NTOT];
__device__ int   g_counts[2][NTOT];
__device__ int   g_csrsrc[2][ETOT];

// ---------------- packed f32x2 helpers (FFMA2: 2x fp32 FMA rate on sm_103a) --------
__device__ __forceinline__ unsigned long long pack2(float x, float y) {
    unsigned long long r;
    asm("mov.b64 %0, {%1, %2};" : "=l"(r) : "f"(x), "f"(y));
    return r;
}
__device__ __forceinline__ void ffma2(unsigned long long& d, unsigned long long a,
                                      unsigned long long b) {
    asm("fma.rn.f32x2 %0, %1, %2, %3;" : "=l"(d) : "l"(a), "l"(b), "l"(d));
}
__device__ __forceinline__ float2 unpack2(unsigned long long v) {
    float2 r;
    asm("mov.b64 {%0, %1}, %2;" : "=f"(r.x), "=f"(r.y) : "l"(v));
    return r;
}

// ---------------- CSR build ----------------
__global__ void zero2_k(int* __restrict__ c)
{
    int t = blockIdx.x * blockDim.x + threadIdx.x;
    if (t < 2 * NTOT) c[t] = 0;
}

__global__ void count_k(const int* __restrict__ dst, int* __restrict__ counts)
{
    int e = blockIdx.x * blockDim.x + threadIdx.x;
    if (e < ETOT) atomicAdd(&counts[dst[e]], 1);
}

__global__ void scan_k(const int* __restrict__ counts, int* __restrict__ rowptr,
                       int* __restrict__ cursor)
{
    __shared__ int warp_sums[32];
    __shared__ int s_carry;
    int tid = threadIdx.x, lane = tid & 31, wid = tid >> 5;
    int nw = blockDim.x >> 5;
    if (tid == 0) s_carry = 0;
    __syncthreads();
    for (int base = 0; base < NTOT; base += blockDim.x) {
        int i = base + tid;
        int v = (i < NTOT) ? counts[i] : 0;
        int x = v;
#pragma unroll
        for (int o = 1; o < 32; o <<= 1) {
            int y = __shfl_up_sync(~0u, x, o);
            if (lane >= o) x += y;
        }
        if (lane == 31) warp_sums[wid] = x;
        __syncthreads();
        if (wid == 0) {
            int s = (lane < nw) ? warp_sums[lane] : 0;
#pragma unroll
            for (int o = 1; o < 32; o <<= 1) {
                int y = __shfl_up_sync(~0u, s, o);
                if (lane >= o) s += y;
            }
            warp_sums[lane] = s;
        }
        __syncthreads();
        int woff = (wid == 0) ? 0 : warp_sums[wid - 1];
        int incl = x + woff;
        int excl = incl - v;
        int carry = s_carry;
        if (i < NTOT) { rowptr[i] = carry + excl; cursor[i] = carry + excl; }
        __syncthreads();
        if (tid == blockDim.x - 1) s_carry = carry + incl;
        __syncthreads();
    }
    if (tid == 0) rowptr[NTOT] = s_carry;
}

__global__ void scatter_k(const int* __restrict__ src, const int* __restrict__ dst,
                          int* __restrict__ cursor, int* __restrict__ csrsrc)
{
    int e = blockIdx.x * blockDim.x + threadIdx.x;
    if (e >= ETOT) return;
    int pos = atomicAdd(&cursor[dst[e]], 1);
    csrsrc[pos] = src[e];
}

// ---------------- 64x64 tile fp32 GEMM with FFMA2 (small-N cases) ----------------
__global__ void gemm64(const float* __restrict__ A, const float* __restrict__ B,
                       const float* __restrict__ bias, float* __restrict__ C,
                       int M, int K, int N)
{
    __shared__ float As[16][65];
    __shared__ float Bs[16][64];
    int tid = threadIdx.x;
    int rowBase = blockIdx.y * 64;
    int colBase = blockIdx.x * 64;
    int tx = tid & 15, ty = tid >> 4;
    int arow = tid >> 2, acol = (tid & 3) << 2;
    int brow = tid >> 4, bcol = (tid & 15) << 2;

    unsigned long long acc[4][2];
#pragma unroll
    for (int i = 0; i < 4; i++) { acc[i][0] = 0ull; acc[i][1] = 0ull; }

    for (int k0 = 0; k0 < K; k0 += 16) {
        float4 av = make_float4(0.f, 0.f, 0.f, 0.f);
        if (rowBase + arow < M)
            av = *reinterpret_cast<const float4*>(A + (size_t)(rowBase + arow) * K + k0 + acol);
        As[acol + 0][arow] = av.x; As[acol + 1][arow] = av.y;
        As[acol + 2][arow] = av.z; As[acol + 3][arow] = av.w;
        float4 bv = make_float4(0.f, 0.f, 0.f, 0.f);
        if (colBase + bcol < N)
            bv = *reinterpret_cast<const float4*>(B + (size_t)(k0 + brow) * N + colBase + bcol);
        *reinterpret_cast<float4*>(&Bs[brow][bcol]) = bv;
        __syncthreads();
#pragma unroll
        for (int k = 0; k < 16; k++) {
            float a0 = As[k][(ty << 2) + 0], a1 = As[k][(ty << 2) + 1];
            float a2 = As[k][(ty << 2) + 2], a3 = As[k][(ty << 2) + 3];
            unsigned long long b01 = *reinterpret_cast<const unsigned long long*>(&Bs[k][(tx << 2) + 0]);
            unsigned long long b23 = *reinterpret_cast<const unsigned long long*>(&Bs[k][(tx << 2) + 2]);
            unsigned long long p0 = pack2(a0, a0), p1 = pack2(a1, a1);
            unsigned long long p2 = pack2(a2, a2), p3 = pack2(a3, a3);
            ffma2(acc[0][0], p0, b01); ffma2(acc[0][1], p0, b23);
            ffma2(acc[1][0], p1, b01); ffma2(acc[1][1], p1, b23);
            ffma2(acc[2][0], p2, b01); ffma2(acc[2][1], p2, b23);
            ffma2(acc[3][0], p3, b01); ffma2(acc[3][1], p3, b23);
        }
        __syncthreads();
    }
#pragma unroll
    for (int i = 0; i < 4; i++) {
        int r = rowBase + (ty << 2) + i;
        if (r >= M) continue;
        float2 u0 = unpack2(acc[i][0]);
        float2 u1 = unpack2(acc[i][1]);
        float vals[4] = {u0.x, u0.y, u1.x, u1.y};
#pragma unroll
        for (int j = 0; j < 4; j++) {
            int c = colBase + (tx << 2) + j;
            if (c < N) C[(size_t)r * N + c] = vals[j] + (bias ? bias[c] : 0.f);
        }
    }
}

// ---------------- 128x128 tile fp32 GEMM (exact R4 champion shape) -----------------
__global__ void __launch_bounds__(256, 2)
gemm128(const float* __restrict__ A, const float* __restrict__ B,
        float* __restrict__ C, int M, int K, int N,
        long long bStride, long long cStride)
{
    __shared__ float As[8][132];
    __shared__ float Bs[8][128];
    const float* Bp = B + (long long)blockIdx.z * bStride;
    float* Cp = C + (long long)blockIdx.z * cStride;

    int tid = threadIdx.x;
    int rb = blockIdx.y * 128, cb = blockIdx.x * 128;
    int tx = tid & 15, ty = tid >> 4;
    int arow = tid >> 1, acol = (tid & 1) << 2;
    int brow = tid >> 5, bcol = (tid & 31) << 2;

    unsigned long long acc[8][4];
#pragma unroll
    for (int i = 0; i < 8; i++)
#pragma unroll
        for (int j = 0; j < 4; j++) acc[i][j] = 0ull;

    for (int k0 = 0; k0 < K; k0 += 8) {
        float4 av = make_float4(0.f, 0.f, 0.f, 0.f);
        if (rb + arow < M)
            av = *reinterpret_cast<const float4*>(A + (size_t)(rb + arow) * K + k0 + acol);
        As[acol + 0][arow] = av.x; As[acol + 1][arow] = av.y;
        As[acol + 2][arow] = av.z; As[acol + 3][arow] = av.w;
        float4 bv = *reinterpret_cast<const float4*>(Bp + (size_t)(k0 + brow) * N + cb + bcol);
        *reinterpret_cast<float4*>(&Bs[brow][bcol]) = bv;
        __syncthreads();
#pragma unroll
        for (int k = 0; k < 8; k++) {
            float a[8];
            *reinterpret_cast<float4*>(a)     = *reinterpret_cast<float4*>(&As[k][ty * 8]);
            *reinterpret_cast<float4*>(a + 4) = *reinterpret_cast<float4*>(&As[k][ty * 8 + 4]);
            unsigned long long b2[4];
            b2[0] = *reinterpret_cast<const unsigned long long*>(&Bs[k][tx * 4]);
            b2[1] = *reinterpret_cast<const unsigned long long*>(&Bs[k][tx * 4 + 2]);
            b2[2] = *reinterpret_cast<const unsigned long long*>(&Bs[k][64 + tx * 4]);
            b2[3] = *reinterpret_cast<const unsigned long long*>(&Bs[k][64 + tx * 4 + 2]);
#pragma unroll
            for (int i = 0; i < 8; i++) {
                unsigned long long aa = pack2(a[i], a[i]);
                ffma2(acc[i][0], aa, b2[0]);
                ffma2(acc[i][1], aa, b2[1]);
                ffma2(acc[i][2], aa, b2[2]);
                ffma2(acc[i][3], aa, b2[3]);
            }
        }
        __syncthreads();
    }
#pragma unroll
    for (int i = 0; i < 8; i++) {
        int r = rb + ty * 8 + i;
        float2 u0 = unpack2(acc[i][0]), u1 = unpack2(acc[i][1]);
        float2 u2 = unpack2(acc[i][2]), u3 = unpack2(acc[i][3]);
        float4 v0 = make_float4(u0.x, u0.y, u1.x, u1.y);
        float4 v1 = make_float4(u2.x, u2.y, u3.x, u3.y);
        *reinterpret_cast<float4*>(Cp + (size_t)r * N + cb + tx * 4) = v0;
        *reinterpret_cast<float4*>(Cp + (size_t)r * N + cb + 64 + tx * 4) = v1;
    }
}

// ---------------- pack layer-2 weights: cols = [W2g0 | W2g1 | res2g0 | res2g1] ------
__global__ void pack_w2_k(const float* __restrict__ W2, const float* __restrict__ res2,
                          float* __restrict__ out)
{
    int idx = blockIdx.x * blockDim.x + threadIdx.x;
    if (idx >= 256 * 64) return;
    int k = idx >> 6, d = idx & 63;
    int g = (d >> 4) & 1;
    int which = d >> 5;
    int dd = d & 15;
    const float* src = which == 0 ? W2 : res2;
    out[idx] = src[(size_t)g * 256 * 16 + k * 16 + dd];
}

// ---------------- attention scores: warp per (node, head) ----------------
__global__ void scores_k(const float* __restrict__ feat, int stride,
                         const float* __restrict__ al, const float* __restrict__ ar,
                         float* __restrict__ el, float* __restrict__ er, int H, int D)
{
    int n = blockIdx.x;
    int wid = threadIdx.x >> 5;
    int lane = threadIdx.x & 31;
    const float* f = feat + (size_t)n * stride + wid * D;
    float sl = 0.f, sr = 0.f;
    for (int d = lane; d < D; d += 32) {
        float v = f[d];
        sl += v * al[wid * D + d];
        sr += v * ar[wid * D + d];
    }
#pragma unroll
    for (int o = 16; o > 0; o >>= 1) {
        sl += __shfl_down_sync(~0u, sl, o);
        sr += __shfl_down_sync(~0u, sr, o);
    }
    if (lane == 0) { el[n * H + wid] = sl; er[n * H + wid] = sr; }
}

// ---------------- edge softmax (CSR, warp per dst node) — R4 exact form ------------
template <int H>
__global__ void softmax_k(const int* __restrict__ rowptr, const int* __restrict__ csrsrc,
                          const float* __restrict__ el, const float* __restrict__ er,
                          float* __restrict__ alpha)
{
    int n = blockIdx.x * (blockDim.x >> 5) + (threadIdx.x >> 5);
    int lane = threadIdx.x & 31;
    if (n >= NTOT) return;
    int beg = rowptr[n], end = rowptr[n + 1];
    if (beg == end) return;

    float erh[H];
#pragma unroll
    for (int h = 0; h < H; h++) erh[h] = er[n * H + h];

    float mx[H];
#pragma unroll
    for (int h = 0; h < H; h++) mx[h] = -1e30f;

    for (int p = beg + lane; p < end; p += 32) {
        int s = csrsrc[p];
#pragma unroll
        for (int h = 0; h < H; h++) {
            float e = el[s * H + h] + erh[h];
            e = e > 0.f ? e : 0.2f * e;
            alpha[p * H + h] = e;
            mx[h] = fmaxf(mx[h], e);
        }
    }
#pragma unroll
    for (int h = 0; h < H; h++)
#pragma unroll
        for (int o = 16; o > 0; o >>= 1)
            mx[h] = fmaxf(mx[h], __shfl_xor_sync(~0u, mx[h], o));

    float den[H];
#pragma unroll
    for (int h = 0; h < H; h++) den[h] = 0.f;
    for (int p = beg + lane; p < end; p += 32) {
#pragma unroll
        for (int h = 0; h < H; h++) {
            float x = expf(alpha[p * H + h] - mx[h]);
            alpha[p * H + h] = x;
            den[h] += x;
        }
    }
#pragma unroll
    for (int h = 0; h < H; h++)
#pragma unroll
        for (int o = 16; o > 0; o >>= 1)
            den[h] += __shfl_xor_sync(~0u, den[h], o);

    float inv[H];
#pragma unroll
    for (int h = 0; h < H; h++) inv[h] = 1.f / den[h];
    for (int p = beg + lane; p < end; p += 32) {
#pragma unroll
        for (int h = 0; h < H; h++) alpha[p * H + h] *= inv[h];
    }
}

// ---------------- fused dual-graph aggregation + epilogue (HD=256) — R4 exact ------
__global__ void aggr256_k(const int* __restrict__ rp0, const int* __restrict__ cs0,
                          const float* __restrict__ a0, const float* __restrict__ f0,
                          const int* __restrict__ rp1, const int* __restrict__ cs1,
                          const float* __restrict__ a1, const float* __restrict__ f1,
                          const float* __restrict__ h, const float* __restrict__ bias0,
                          const float* __restrict__ bias1, const float* __restrict__ mixw,
                          int layer, int useRes, float* __restrict__ out)
{
    int n = blockIdx.x;
    int d = threadIdx.x;
    int head = d >> 6;

    float acc0 = 0.f, acc1 = 0.f;
    {
        int p = rp0[n], e = rp0[n + 1];
        for (; p + 2 <= e; p += 2) {
            int s0 = __ldg(&cs0[p]),     s1 = __ldg(&cs0[p + 1]);
            float w0 = __ldg(&a0[p * 4 + head]);
            float w1 = __ldg(&a0[(p + 1) * 4 + head]);
            float v0 = f0[(size_t)s0 * 256 + d];
            float v1 = f0[(size_t)s1 * 256 + d];
            acc0 += v0 * w0 + v1 * w1;
        }
        if (p < e) {
            int s = __ldg(&cs0[p]);
            acc0 += f0[(size_t)s * 256 + d] * __ldg(&a0[p * 4 + head]);
        }
    }
    {
        int p = rp1[n], e = rp1[n + 1];
        for (; p + 2 <= e; p += 2) {
            int s0 = __ldg(&cs1[p]),     s1 = __ldg(&cs1[p + 1]);
            float w0 = __ldg(&a1[p * 4 + head]);
            float w1 = __ldg(&a1[(p + 1) * 4 + head]);
            float v0 = f1[(size_t)s0 * 256 + d];
            float v1 = f1[(size_t)s1 * 256 + d];
            acc1 += v0 * w0 + v1 * w1;
        }
        if (p < e) {
            int s = __ldg(&cs1[p]);
            acc1 += f1[(size_t)s * 256 + d] * __ldg(&a1[p * 4 + head]);
        }
    }

    float res = useRes ? h[(size_t)n * 256 + d] : 0.f;
    float v0 = acc0 + res + bias0[d];
    float v1 = acc1 + res + bias1[d];
    v0 = v0 > 0.f ? v0 : expm1f(v0);
    v1 = v1 > 0.f ? v1 : expm1f(v1);

    int ty = (n < NTYPE0) ? 0 : 1;
    float m0 = mixw[ty * 6 + layer * 2 + 0];
    float m1 = mixw[ty * 6 + layer * 2 + 1];
    float mxw = fmaxf(m0, m1);
    float e0 = expf(m0 - mxw), e1 = expf(m1 - mxw);
    float inv = 1.f / (e0 + e1);
    out[(size_t)n * 256 + d] = v0 * (e0 * inv) + v1 * (e1 * inv);
}

// ---------------- layer 2 aggregation (H=1, D=16), packed l2 buffer — R4 exact -----
__global__ void aggr16_k(const int* __restrict__ rp0, const int* __restrict__ cs0,
                         const float* __restrict__ a0,
                         const int* __restrict__ rp1, const int* __restrict__ cs1,
                         const float* __restrict__ a1,
                         const float* __restrict__ l2, const float* __restrict__ b2,
                         const float* __restrict__ mixw, float* __restrict__ logits)
{
    int n = blockIdx.x * 16 + (threadIdx.x >> 4);
    int d = threadIdx.x & 15;
    if (n >= NTOT) return;

    float acc0 = 0.f, acc1 = 0.f;
    int b = rp0[n], e = rp0[n + 1];
    for (int p = b; p < e; p++)
        acc0 += l2[(size_t)__ldg(&cs0[p]) * 64 + d] * __ldg(&a0[p]);
    b = rp1[n]; e = rp1[n + 1];
    for (int p = b; p < e; p++)
        acc1 += l2[(size_t)__ldg(&cs1[p]) * 64 + 16 + d] * __ldg(&a1[p]);

    float v0 = acc0 + l2[(size_t)n * 64 + 32 + d] + b2[d];
    float v1 = acc1 + l2[(size_t)n * 64 + 48 + d] + b2[16 + d];

    int ty = (n < NTYPE0) ? 0 : 1;
    float m0 = mixw[ty * 6 + 4 + 0];
    float m1 = mixw[ty * 6 + 4 + 1];
    float mxw = fmaxf(m0, m1);
    float e0 = expf(m0 - mxw), e1 = expf(m1 - mxw);
    float inv = 1.f / (e0 + e1);
    logits[(size_t)n * 16 + d] = v0 * (e0 * inv) + v1 * (e1 * inv);
}

// ---------------- host orchestration (dual-stream fork/join) ----------------
extern "C" void kernel_launch(void* const* d_in, const int* in_sizes, int n_in,
                              void* d_out, int out_size)
{
    const float* features0 = (const float*)d_in[0];
    const float* features1 = (const float*)d_in[1];
    const float* fc_w0 = (const float*)d_in[2];
    const float* fc_b0 = (const float*)d_in[3];
    const float* fc_w1 = (const float*)d_in[4];
    const float* fc_b1 = (const float*)d_in[5];
    const float* mix_w = (const float*)d_in[6];
    const float* W0  = (const float*)d_in[7];
    const float* al0 = (const float*)d_in[8];
    const float* ar0 = (const float*)d_in[9];
    const float* b0  = (const float*)d_in[10];
    const float* W1  = (const float*)d_in[11];
    const float* al1 = (const float*)d_in[12];
    const float* ar1 = (const float*)d_in[13];
    const float* b1  = (const float*)d_in[14];
    const float* W2  = (const float*)d_in[15];
    const float* al2 = (const float*)d_in[16];
    const float* ar2 = (const float*)d_in[17];
    const float* b2  = (const float*)d_in[18];
    const float* res2= (const float*)d_in[19];
    const int* srcs[2] = {(const int*)d_in[20], (const int*)d_in[22]};
    const int* dsts[2] = {(const int*)d_in[21], (const int*)d_in[23]};

    float *h, *acc, *featb, *l2out, *w2pack, *elp, *erp, *alphap;
    int *rowptrp, *cursorp, *countsp, *csrsrcp;
    cudaGetSymbolAddress((void**)&h,      g_h);
    cudaGetSymbolAddress((void**)&acc,    g_acc);
    cudaGetSymbolAddress((void**)&featb,  g_feat);
    cudaGetSymbolAddress((void**)&l2out,  g_l2out);
    cudaGetSymbolAddress((void**)&w2pack, g_w2pack);
    cudaGetSymbolAddress((void**)&elp,    g_el);
    cudaGetSymbolAddress((void**)&erp,    g_er);
    cudaGetSymbolAddress((void**)&alphap, g_alpha);
    cudaGetSymbolAddress((void**)&rowptrp, g_rowptr);
    cudaGetSymbolAddress((void**)&cursorp, g_cursor);
    cudaGetSymbolAddress((void**)&countsp, g_counts);
    cudaGetSymbolAddress((void**)&csrsrcp, g_csrsrc);

    float* feat[2]  = {featb, featb + (size_t)NPAD * 256};
    float* el[2]    = {elp, elp + NTOT * 4};
    float* er[2]    = {erp, erp + NTOT * 4};
    float* alpha[2] = {alphap, alphap + ETOT * 4};
    int* rowptr[2]  = {rowptrp, rowptrp + NTOT + 1};
    int* cursor[2]  = {cursorp, cursorp + NTOT};
    int* counts[2]  = {countsp, countsp + NTOT};
    int* csrsrc[2]  = {csrsrcp, csrsrcp + ETOT};

    const int TPB = 256;
    const int N1n = NTOT - NTYPE0;
    const int EB = (ETOT + TPB - 1) / TPB;
    const int MB = (NTOT + 127) / 128;

    // one side stream + events, created once (first call is the uncaptured
    // correctness run; capture on later calls sees only launches/event nodes)
    static cudaStream_t s2 = nullptr;
    static cudaEvent_t evFork = nullptr, evCsr = nullptr, evScore = nullptr, evJoin = nullptr;
    if (s2 == nullptr) {
        cudaStreamCreateWithFlags(&s2, cudaStreamNonBlocking);
        cudaEventCreateWithFlags(&evFork,  cudaEventDisableTiming);
        cudaEventCreateWithFlags(&evCsr,   cudaEventDisableTiming);
        cudaEventCreateWithFlags(&evScore, cudaEventDisableTiming);
        cudaEventCreateWithFlags(&evJoin,  cudaEventDisableTiming);
    }
    cudaStream_t s0 = 0;

    // ---- fork: CSR build + weight pack on s2, FC/projection chain on s0 ----
    cudaEventRecord(evFork, s0);
    cudaStreamWaitEvent(s2, evFork, 0);

    zero2_k<<<(2 * NTOT + TPB - 1) / TPB, TPB, 0, s2>>>(countsp);
    count_k<<<EB, TPB, 0, s2>>>(dsts[0], counts[0]);
    count_k<<<EB, TPB, 0, s2>>>(dsts[1], counts[1]);
    scan_k<<<1, 1024, 0, s2>>>(counts[0], rowptr[0], cursor[0]);
    scan_k<<<1, 1024, 0, s2>>>(counts[1], rowptr[1], cursor[1]);
    scatter_k<<<EB, TPB, 0, s2>>>(srcs[0], dsts[0], cursor[0], csrsrc[0]);
    scatter_k<<<EB, TPB, 0, s2>>>(srcs[1], dsts[1], cursor[1], csrsrc[1]);
    pack_w2_k<<<64, 256, 0, s2>>>(W2, res2, w2pack);
    cudaEventRecord(evCsr, s2);

    gemm64<<<dim3(1, (NTYPE0 + 63) / 64), TPB, 0, s0>>>(features0, fc_w0, fc_b0, h,
                                                        NTYPE0, 128, 64);
    gemm64<<<dim3(1, (N1n + 63) / 64), TPB, 0, s0>>>(features1, fc_w1, fc_b1,
                                                     h + (size_t)NTYPE0 * 64,
                                                     N1n, 128, 64);
    gemm128<<<dim3(2, MB, 2), 256, 0, s0>>>(h, W0, featb, NTOT, 64, 256,
                                            (long long)64 * 256, (long long)NPAD * 256);

    // join CSR into main before any softmax / aggregation use
    cudaStreamWaitEvent(s0, evCsr, 0);

    float* cur = h;
    float* nxt = acc;
    for (int l = 0; l < 2; l++) {
        int Kin = (l == 0) ? 64 : 256;
        const float* Wl  = (l == 0) ? W0 : W1;
        const float* all = (l == 0) ? al0 : al1;
        const float* arl = (l == 0) ? ar0 : ar1;
        const float* bl  = (l == 0) ? b0 : b1;
        if (l != 0)
            gemm128<<<dim3(2, MB, 2), 256, 0, s0>>>(cur, Wl, featb, NTOT, Kin, 256,
                                                    (long long)Kin * 256,
                                                    (long long)NPAD * 256);
        scores_k<<<NTOT, 128, 0, s0>>>(feat[0], 256, all, arl, el[0], er[0], 4, 64);
        scores_k<<<NTOT, 128, 0, s0>>>(feat[1], 256, all + 256, arl + 256, el[1], er[1], 4, 64);

        // graph-1 softmax runs on s2 concurrently with graph-0 softmax on s0
        cudaEventRecord(evScore, s0);
        cudaStreamWaitEvent(s2, evScore, 0);
        softmax_k<4><<<(NTOT + 7) / 8, 256, 0, s0>>>(rowptr[0], csrsrc[0], el[0], er[0], alpha[0]);
        softmax_k<4><<<(NTOT + 7) / 8, 256, 0, s2>>>(rowptr[1], csrsrc[1], el[1], er[1], alpha[1]);
        cudaEventRecord(evJoin, s2);
        cudaStreamWaitEvent(s0, evJoin, 0);

        aggr256_k<<<NTOT, 256, 0, s0>>>(rowptr[0], csrsrc[0], alpha[0], feat[0],
                                        rowptr[1], csrsrc[1], alpha[1], feat[1],
                                        cur, bl, bl + 256, mix_w, l, (l == 1) ? 1 : 0, nxt);
        float* t = cur; cur = nxt; nxt = t;
    }

    // ---- layer 2 (H=1, D=16): single packed N=64 GEMM, softmax, aggregate ----
    gemm64<<<dim3(1, (NTOT + 63) / 64), TPB, 0, s0>>>(cur, w2pack, nullptr, l2out, NTOT, 256, 64);
    scores_k<<<NTOT, 32, 0, s0>>>(l2out, 64, al2, ar2, el[0], er[0], 1, 16);
    scores_k<<<NTOT, 32, 0, s0>>>(l2out + 16, 64, al2 + 16, ar2 + 16, el[1], er[1], 1, 16);

    cudaEventRecord(evScore, s0);
    cudaStreamWaitEvent(s2, evScore, 0);
    softmax_k<1><<<(NTOT + 7) / 8, 256, 0, s0>>>(rowptr[0], csrsrc[0], el[0], er[0], alpha[0]);
    softmax_k<1><<<(NTOT + 7) / 8, 256, 0, s2>>>(rowptr[1], csrsrc[1], el[1], er[1], alpha[1]);
    cudaEventRecord(evJoin, s2);
    cudaStreamWaitEvent(s0, evJoin, 0);

    aggr16_k<<<(NTOT + 15) / 16, 256, 0, s0>>>(rowptr[0], csrsrc[0], alpha[0],
                                               rowptr[1], csrsrc[1], alpha[1],
                                               l2out, b2, mix_w, (float*)d_out);
}

// round 15
// speedup vs baseline: 1.3142x; 1.0103x over previous
#include <cuda_runtime.h>
#include <math.h>

#define NTOT   50000
#define NTYPE0 30000
#define ETOT   400000
#define NPAD   50048
#define SCAN_B 256
#define SCAN_NB ((NTOT + SCAN_B - 1) / SCAN_B)   // 196

// ---------------- static scratch ----------------
__device__ float g_h[NPAD * 256];
__device__ float g_acc[NPAD * 256];
__device__ float g_feat[2 * NPAD * 256];
__device__ float g_l2out[NPAD * 64];
__device__ float g_w2pack[256 * 64];
__device__ float g_el[2][NTOT * 4];
__device__ float g_er[2][NTOT * 4];
__device__ float g_alpha[2][ETOT * 4];
__device__ int   g_rowptr[2][NTOT + 1];
__device__ int   g_cursor[2][NTOT];
__device__ int   g_counts[2][NTOT];
__device__ int   g_bsums[2][SCAN_NB + 1];
__device__ int   g_csrsrc[2][ETOT];

// ---------------- packed f32x2 helpers (FFMA2: 2x fp32 FMA rate on sm_103a) --------
__device__ __forceinline__ unsigned long long pack2(float x, float y) {
    unsigned long long r;
    asm("mov.b64 %0, {%1, %2};" : "=l"(r) : "f"(x), "f"(y));
    return r;
}
__device__ __forceinline__ void ffma2(unsigned long long& d, unsigned long long a,
                                      unsigned long long b) {
    asm("fma.rn.f32x2 %0, %1, %2, %3;" : "=l"(d) : "l"(a), "l"(b), "l"(d));
}
__device__ __forceinline__ float2 unpack2(unsigned long long v) {
    float2 r;
    asm("mov.b64 {%0, %1}, %2;" : "=f"(r.x), "=f"(r.y) : "l"(v));
    return r;
}

// ---------------- CSR build ----------------
__global__ void zero_k(int* __restrict__ c, int count)
{
    int t = blockIdx.x * blockDim.x + threadIdx.x;
    if (t < count) c[t] = 0;
}

__global__ void count_k(const int* __restrict__ dst, int* __restrict__ counts)
{
    int e = blockIdx.x * blockDim.x + threadIdx.x;
    if (e < ETOT) atomicAdd(&counts[dst[e]], 1);
}

// phase A: per-block exclusive scan of a 256-chunk; emit block total
__global__ void scanA_k(const int* __restrict__ counts, int* __restrict__ partial,
                        int* __restrict__ bsums)
{
    __shared__ int wsum[8];
    int b = blockIdx.x;
    int tid = threadIdx.x, lane = tid & 31, wid = tid >> 5;
    int i = b * SCAN_B + tid;
    int v = (i < NTOT) ? counts[i] : 0;
    int x = v;
#pragma unroll
    for (int o = 1; o < 32; o <<= 1) {
        int y = __shfl_up_sync(~0u, x, o);
        if (lane >= o) x += y;
    }
    if (lane == 31) wsum[wid] = x;
    __syncthreads();
    if (wid == 0 && lane < 8) {
        int s = wsum[lane];
#pragma unroll
        for (int o = 1; o < 8; o <<= 1) {
            int y = __shfl_up_sync(0xFF, s, o);
            if (lane >= o) s += y;
        }
        wsum[lane] = s;
    }
    __syncthreads();
    int woff = (wid == 0) ? 0 : wsum[wid - 1];
    int excl = x - v + woff;
    if (i < NTOT) partial[i] = excl;
    if (tid == SCAN_B - 1) bsums[b] = excl + v;
}

// phase B: single block scans the block sums (exclusive)
__global__ void scanB_k(int* __restrict__ bsums)
{
    __shared__ int wsum[8];
    int tid = threadIdx.x, lane = tid & 31, wid = tid >> 5;
    int v = (tid < SCAN_NB) ? bsums[tid] : 0;
    int x = v;
#pragma unroll
    for (int o = 1; o < 32; o <<= 1) {
        int y = __shfl_up_sync(~0u, x, o);
        if (lane >= o) x += y;
    }
    if (lane == 31) wsum[wid] = x;
    __syncthreads();
    if (wid == 0 && lane < 8) {
        int s = wsum[lane];
#pragma unroll
        for (int o = 1; o < 8; o <<= 1) {
            int y = __shfl_up_sync(0xFF, s, o);
            if (lane >= o) s += y;
        }
        wsum[lane] = s;
    }
    __syncthreads();
    int woff = (wid == 0) ? 0 : wsum[wid - 1];
    int excl = x - v + woff;
    if (tid < SCAN_NB) bsums[tid] = excl;
    if (tid == SCAN_NB - 1) bsums[SCAN_NB] = excl + v;  // total
}

// phase C: add block offsets, write rowptr + cursor
__global__ void scanC_k(const int* __restrict__ partial, const int* __restrict__ bsums,
                        int* __restrict__ rowptr, int* __restrict__ cursor)
{
    int b = blockIdx.x;
    int i = b * SCAN_B + threadIdx.x;
    if (i < NTOT) {
        int v = partial[i] + bsums[b];
        rowptr[i] = v;
        cursor[i] = v;
    }
    if (i == 0) rowptr[NTOT] = bsums[SCAN_NB];
}

__global__ void scatter_k(const int* __restrict__ src, const int* __restrict__ dst,
                          int* __restrict__ cursor, int* __restrict__ csrsrc)
{
    int e = blockIdx.x * blockDim.x + threadIdx.x;
    if (e >= ETOT) return;
    int pos = atomicAdd(&cursor[dst[e]], 1);
    csrsrc[pos] = src[e];
}

// ---------------- 64x64 tile fp32 GEMM with FFMA2 (small-N cases) ----------------
__global__ void gemm64(const float* __restrict__ A, const float* __restrict__ B,
                       const float* __restrict__ bias, float* __restrict__ C,
                       int M, int K, int N)
{
    __shared__ float As[16][65];
    __shared__ float Bs[16][64];
    int tid = threadIdx.x;
    int rowBase = blockIdx.y * 64;
    int colBase = blockIdx.x * 64;
    int tx = tid & 15, ty = tid >> 4;
    int arow = tid >> 2, acol = (tid & 3) << 2;
    int brow = tid >> 4, bcol = (tid & 15) << 2;

    unsigned long long acc[4][2];
#pragma unroll
    for (int i = 0; i < 4; i++) { acc[i][0] = 0ull; acc[i][1] = 0ull; }

    for (int k0 = 0; k0 < K; k0 += 16) {
        float4 av = make_float4(0.f, 0.f, 0.f, 0.f);
        if (rowBase + arow < M)
            av = *reinterpret_cast<const float4*>(A + (size_t)(rowBase + arow) * K + k0 + acol);
        As[acol + 0][arow] = av.x; As[acol + 1][arow] = av.y;
        As[acol + 2][arow] = av.z; As[acol + 3][arow] = av.w;
        float4 bv = make_float4(0.f, 0.f, 0.f, 0.f);
        if (colBase + bcol < N)
            bv = *reinterpret_cast<const float4*>(B + (size_t)(k0 + brow) * N + colBase + bcol);
        *reinterpret_cast<float4*>(&Bs[brow][bcol]) = bv;
        __syncthreads();
#pragma unroll
        for (int k = 0; k < 16; k++) {
            float a0 = As[k][(ty << 2) + 0], a1 = As[k][(ty << 2) + 1];
            float a2 = As[k][(ty << 2) + 2], a3 = As[k][(ty << 2) + 3];
            unsigned long long b01 = *reinterpret_cast<const unsigned long long*>(&Bs[k][(tx << 2) + 0]);
            unsigned long long b23 = *reinterpret_cast<const unsigned long long*>(&Bs[k][(tx << 2) + 2]);
            unsigned long long p0 = pack2(a0, a0), p1 = pack2(a1, a1);
            unsigned long long p2 = pack2(a2, a2), p3 = pack2(a3, a3);
            ffma2(acc[0][0], p0, b01); ffma2(acc[0][1], p0, b23);
            ffma2(acc[1][0], p1, b01); ffma2(acc[1][1], p1, b23);
            ffma2(acc[2][0], p2, b01); ffma2(acc[2][1], p2, b23);
            ffma2(acc[3][0], p3, b01); ffma2(acc[3][1], p3, b23);
        }
        __syncthreads();
    }
#pragma unroll
    for (int i = 0; i < 4; i++) {
        int r = rowBase + (ty << 2) + i;
        if (r >= M) continue;
        float2 u0 = unpack2(acc[i][0]);
        float2 u1 = unpack2(acc[i][1]);
        float vals[4] = {u0.x, u0.y, u1.x, u1.y};
#pragma unroll
        for (int j = 0; j < 4; j++) {
            int c = colBase + (tx << 2) + j;
            if (c < N) C[(size_t)r * N + c] = vals[j] + (bias ? bias[c] : 0.f);
        }
    }
}

// ---------------- 128x128 tile fp32 GEMM (exact R4 champion shape) -----------------
__global__ void __launch_bounds__(256, 2)
gemm128(const float* __restrict__ A, const float* __restrict__ B,
        float* __restrict__ C, int M, int K, int N,
        long long bStride, long long cStride)
{
    __shared__ float As[8][132];
    __shared__ float Bs[8][128];
    const float* Bp = B + (long long)blockIdx.z * bStride;
    float* Cp = C + (long long)blockIdx.z * cStride;

    int tid = threadIdx.x;
    int rb = blockIdx.y * 128, cb = blockIdx.x * 128;
    int tx = tid & 15, ty = tid >> 4;
    int arow = tid >> 1, acol = (tid & 1) << 2;
    int brow = tid >> 5, bcol = (tid & 31) << 2;

    unsigned long long acc[8][4];
#pragma unroll
    for (int i = 0; i < 8; i++)
#pragma unroll
        for (int j = 0; j < 4; j++) acc[i][j] = 0ull;

    for (int k0 = 0; k0 < K; k0 += 8) {
        float4 av = make_float4(0.f, 0.f, 0.f, 0.f);
        if (rb + arow < M)
            av = *reinterpret_cast<const float4*>(A + (size_t)(rb + arow) * K + k0 + acol);
        As[acol + 0][arow] = av.x; As[acol + 1][arow] = av.y;
        As[acol + 2][arow] = av.z; As[acol + 3][arow] = av.w;
        float4 bv = *reinterpret_cast<const float4*>(Bp + (size_t)(k0 + brow) * N + cb + bcol);
        *reinterpret_cast<float4*>(&Bs[brow][bcol]) = bv;
        __syncthreads();
#pragma unroll
        for (int k = 0; k < 8; k++) {
            float a[8];
            *reinterpret_cast<float4*>(a)     = *reinterpret_cast<float4*>(&As[k][ty * 8]);
            *reinterpret_cast<float4*>(a + 4) = *reinterpret_cast<float4*>(&As[k][ty * 8 + 4]);
            unsigned long long b2[4];
            b2[0] = *reinterpret_cast<const unsigned long long*>(&Bs[k][tx * 4]);
            b2[1] = *reinterpret_cast<const unsigned long long*>(&Bs[k][tx * 4 + 2]);
            b2[2] = *reinterpret_cast<const unsigned long long*>(&Bs[k][64 + tx * 4]);
            b2[3] = *reinterpret_cast<const unsigned long long*>(&Bs[k][64 + tx * 4 + 2]);
#pragma unroll
            for (int i = 0; i < 8; i++) {
                unsigned long long aa = pack2(a[i], a[i]);
                ffma2(acc[i][0], aa, b2[0]);
                ffma2(acc[i][1], aa, b2[1]);
                ffma2(acc[i][2], aa, b2[2]);
                ffma2(acc[i][3], aa, b2[3]);
            }
        }
        __syncthreads();
    }
#pragma unroll
    for (int i = 0; i < 8; i++) {
        int r = rb + ty * 8 + i;
        float2 u0 = unpack2(acc[i][0]), u1 = unpack2(acc[i][1]);
        float2 u2 = unpack2(acc[i][2]), u3 = unpack2(acc[i][3]);
        float4 v0 = make_float4(u0.x, u0.y, u1.x, u1.y);
        float4 v1 = make_float4(u2.x, u2.y, u3.x, u3.y);
        *reinterpret_cast<float4*>(Cp + (size_t)r * N + cb + tx * 4) = v0;
        *reinterpret_cast<float4*>(Cp + (size_t)r * N + cb + 64 + tx * 4) = v1;
    }
}

// ---------------- pack layer-2 weights: cols = [W2g0 | W2g1 | res2g0 | res2g1] ------
__global__ void pack_w2_k(const float* __restrict__ W2, const float* __restrict__ res2,
                          float* __restrict__ out)
{
    int idx = blockIdx.x * blockDim.x + threadIdx.x;
    if (idx >= 256 * 64) return;
    int k = idx >> 6, d = idx & 63;
    int g = (d >> 4) & 1;
    int which = d >> 5;
    int dd = d & 15;
    const float* src = which == 0 ? W2 : res2;
    out[idx] = src[(size_t)g * 256 * 16 + k * 16 + dd];
}

// ---------------- attention scores: warp per (node, head) ----------------
__global__ void scores_k(const float* __restrict__ feat, int stride,
                         const float* __restrict__ al, const float* __restrict__ ar,
                         float* __restrict__ el, float* __restrict__ er, int H, int D)
{
    int n = blockIdx.x;
    int wid = threadIdx.x >> 5;
    int lane = threadIdx.x & 31;
    const float* f = feat + (size_t)n * stride + wid * D;
    float sl = 0.f, sr = 0.f;
    for (int d = lane; d < D; d += 32) {
        float v = f[d];
        sl += v * al[wid * D + d];
        sr += v * ar[wid * D + d];
    }
#pragma unroll
    for (int o = 16; o > 0; o >>= 1) {
        sl += __shfl_down_sync(~0u, sl, o);
        sr += __shfl_down_sync(~0u, sr, o);
    }
    if (lane == 0) { el[n * H + wid] = sl; er[n * H + wid] = sr; }
}

// ---------------- edge softmax (CSR, warp per dst node) — R4 exact form ------------
template <int H>
__global__ void softmax_k(const int* __restrict__ rowptr, const int* __restrict__ csrsrc,
                          const float* __restrict__ el, const float* __restrict__ er,
                          float* __restrict__ alpha)
{
    int n = blockIdx.x * (blockDim.x >> 5) + (threadIdx.x >> 5);
    int lane = threadIdx.x & 31;
    if (n >= NTOT) return;
    int beg = rowptr[n], end = rowptr[n + 1];
    if (beg == end) return;

    float erh[H];
#pragma unroll
    for (int h = 0; h < H; h++) erh[h] = er[n * H + h];

    float mx[H];
#pragma unroll
    for (int h = 0; h < H; h++) mx[h] = -1e30f;

    for (int p = beg + lane; p < end; p += 32) {
        int s = csrsrc[p];
#pragma unroll
        for (int h = 0; h < H; h++) {
            float e = el[s * H + h] + erh[h];
            e = e > 0.f ? e : 0.2f * e;
            alpha[p * H + h] = e;
            mx[h] = fmaxf(mx[h], e);
        }
    }
#pragma unroll
    for (int h = 0; h < H; h++)
#pragma unroll
        for (int o = 16; o > 0; o >>= 1)
            mx[h] = fmaxf(mx[h], __shfl_xor_sync(~0u, mx[h], o));

    float den[H];
#pragma unroll
    for (int h = 0; h < H; h++) den[h] = 0.f;
    for (int p = beg + lane; p < end; p += 32) {
#pragma unroll
        for (int h = 0; h < H; h++) {
            float x = expf(alpha[p * H + h] - mx[h]);
            alpha[p * H + h] = x;
            den[h] += x;
        }
    }
#pragma unroll
    for (int h = 0; h < H; h++)
#pragma unroll
        for (int o = 16; o > 0; o >>= 1)
            den[h] += __shfl_xor_sync(~0u, den[h], o);

    float inv[H];
#pragma unroll
    for (int h = 0; h < H; h++) inv[h] = 1.f / den[h];
    for (int p = beg + lane; p < end; p += 32) {
#pragma unroll
        for (int h = 0; h < H; h++) alpha[p * H + h] *= inv[h];
    }
}

// ---------------- fused dual-graph aggregation + epilogue (HD=256) — R4 exact ------
__global__ void aggr256_k(const int* __restrict__ rp0, const int* __restrict__ cs0,
                          const float* __restrict__ a0, const float* __restrict__ f0,
                          const int* __restrict__ rp1, const int* __restrict__ cs1,
                          const float* __restrict__ a1, const float* __restrict__ f1,
                          const float* __restrict__ h, const float* __restrict__ bias0,
                          const float* __restrict__ bias1, const float* __restrict__ mixw,
                          int layer, int useRes, float* __restrict__ out)
{
    int n = blockIdx.x;
    int d = threadIdx.x;
    int head = d >> 6;

    float acc0 = 0.f, acc1 = 0.f;
    {
        int p = rp0[n], e = rp0[n + 1];
        for (; p + 2 <= e; p += 2) {
            int s0 = __ldg(&cs0[p]),     s1 = __ldg(&cs0[p + 1]);
            float w0 = __ldg(&a0[p * 4 + head]);
            float w1 = __ldg(&a0[(p + 1) * 4 + head]);
            float v0 = f0[(size_t)s0 * 256 + d];
            float v1 = f0[(size_t)s1 * 256 + d];
            acc0 += v0 * w0 + v1 * w1;
        }
        if (p < e) {
            int s = __ldg(&cs0[p]);
            acc0 += f0[(size_t)s * 256 + d] * __ldg(&a0[p * 4 + head]);
        }
    }
    {
        int p = rp1[n], e = rp1[n + 1];
        for (; p + 2 <= e; p += 2) {
            int s0 = __ldg(&cs1[p]),     s1 = __ldg(&cs1[p + 1]);
            float w0 = __ldg(&a1[p * 4 + head]);
            float w1 = __ldg(&a1[(p + 1) * 4 + head]);
            float v0 = f1[(size_t)s0 * 256 + d];
            float v1 = f1[(size_t)s1 * 256 + d];
            acc1 += v0 * w0 + v1 * w1;
        }
        if (p < e) {
            int s = __ldg(&cs1[p]);
            acc1 += f1[(size_t)s * 256 + d] * __ldg(&a1[p * 4 + head]);
        }
    }

    float res = useRes ? h[(size_t)n * 256 + d] : 0.f;
    float v0 = acc0 + res + bias0[d];
    float v1 = acc1 + res + bias1[d];
    v0 = v0 > 0.f ? v0 : expm1f(v0);
    v1 = v1 > 0.f ? v1 : expm1f(v1);

    int ty = (n < NTYPE0) ? 0 : 1;
    float m0 = mixw[ty * 6 + layer * 2 + 0];
    float m1 = mixw[ty * 6 + layer * 2 + 1];
    float mxw = fmaxf(m0, m1);
    float e0 = expf(m0 - mxw), e1 = expf(m1 - mxw);
    float inv = 1.f / (e0 + e1);
    out[(size_t)n * 256 + d] = v0 * (e0 * inv) + v1 * (e1 * inv);
}

// ---------------- layer 2 aggregation (H=1, D=16), packed l2 buffer — R4 exact -----
__global__ void aggr16_k(const int* __restrict__ rp0, const int* __restrict__ cs0,
                         const float* __restrict__ a0,
                         const int* __restrict__ rp1, const int* __restrict__ cs1,
                         const float* __restrict__ a1,
                         const float* __restrict__ l2, const float* __restrict__ b2,
                         const float* __restrict__ mixw, float* __restrict__ logits)
{
    int n = blockIdx.x * 16 + (threadIdx.x >> 4);
    int d = threadIdx.x & 15;
    if (n >= NTOT) return;

    float acc0 = 0.f, acc1 = 0.f;
    int b = rp0[n], e = rp0[n + 1];
    for (int p = b; p < e; p++)
        acc0 += l2[(size_t)__ldg(&cs0[p]) * 64 + d] * __ldg(&a0[p]);
    b = rp1[n]; e = rp1[n + 1];
    for (int p = b; p < e; p++)
        acc1 += l2[(size_t)__ldg(&cs1[p]) * 64 + 16 + d] * __ldg(&a1[p]);

    float v0 = acc0 + l2[(size_t)n * 64 + 32 + d] + b2[d];
    float v1 = acc1 + l2[(size_t)n * 64 + 48 + d] + b2[16 + d];

    int ty = (n < NTYPE0) ? 0 : 1;
    float m0 = mixw[ty * 6 + 4 + 0];
    float m1 = mixw[ty * 6 + 4 + 1];
    float mxw = fmaxf(m0, m1);
    float e0 = expf(m0 - mxw), e1 = expf(m1 - mxw);
    float inv = 1.f / (e0 + e1);
    logits[(size_t)n * 16 + d] = v0 * (e0 * inv) + v1 * (e1 * inv);
}

// ---------------- host orchestration (tri-stream fork/join) ----------------
extern "C" void kernel_launch(void* const* d_in, const int* in_sizes, int n_in,
                              void* d_out, int out_size)
{
    const float* features0 = (const float*)d_in[0];
    const float* features1 = (const float*)d_in[1];
    const float* fc_w0 = (const float*)d_in[2];
    const float* fc_b0 = (const float*)d_in[3];
    const float* fc_w1 = (const float*)d_in[4];
    const float* fc_b1 = (const float*)d_in[5];
    const float* mix_w = (const float*)d_in[6];
    const float* W0  = (const float*)d_in[7];
    const float* al0 = (const float*)d_in[8];
    const float* ar0 = (const float*)d_in[9];
    const float* b0  = (const float*)d_in[10];
    const float* W1  = (const float*)d_in[11];
    const float* al1 = (const float*)d_in[12];
    const float* ar1 = (const float*)d_in[13];
    const float* b1  = (const float*)d_in[14];
    const float* W2  = (const float*)d_in[15];
    const float* al2 = (const float*)d_in[16];
    const float* ar2 = (const float*)d_in[17];
    const float* b2  = (const float*)d_in[18];
    const float* res2= (const float*)d_in[19];
    const int* srcs[2] = {(const int*)d_in[20], (const int*)d_in[22]};
    const int* dsts[2] = {(const int*)d_in[21], (const int*)d_in[23]};

    float *h, *acc, *featb, *l2out, *w2pack, *elp, *erp, *alphap;
    int *rowptrp, *cursorp, *countsp, *bsumsp, *csrsrcp;
    cudaGetSymbolAddress((void**)&h,      g_h);
    cudaGetSymbolAddress((void**)&acc,    g_acc);
    cudaGetSymbolAddress((void**)&featb,  g_feat);
    cudaGetSymbolAddress((void**)&l2out,  g_l2out);
    cudaGetSymbolAddress((void**)&w2pack, g_w2pack);
    cudaGetSymbolAddress((void**)&elp,    g_el);
    cudaGetSymbolAddress((void**)&erp,    g_er);
    cudaGetSymbolAddress((void**)&alphap, g_alpha);
    cudaGetSymbolAddress((void**)&rowptrp, g_rowptr);
    cudaGetSymbolAddress((void**)&cursorp, g_cursor);
    cudaGetSymbolAddress((void**)&countsp, g_counts);
    cudaGetSymbolAddress((void**)&bsumsp,  g_bsums);
    cudaGetSymbolAddress((void**)&csrsrcp, g_csrsrc);

    float* feat[2]  = {featb, featb + (size_t)NPAD * 256};
    float* el[2]    = {elp, elp + NTOT * 4};
    float* er[2]    = {erp, erp + NTOT * 4};
    float* alpha[2] = {alphap, alphap + ETOT * 4};
    int* rowptr[2]  = {rowptrp, rowptrp + NTOT + 1};
    int* cursor[2]  = {cursorp, cursorp + NTOT};
    int* counts[2]  = {countsp, countsp + NTOT};
    int* bsums[2]   = {bsumsp, bsumsp + SCAN_NB + 1};
    int* csrsrc[2]  = {csrsrcp, csrsrcp + ETOT};

    const int TPB = 256;
    const int N1n = NTOT - NTYPE0;
    const int EB = (ETOT + TPB - 1) / TPB;
    const int MB = (NTOT + 127) / 128;
    const int NB = (NTOT + TPB - 1) / TPB;

    static cudaStream_t s2 = nullptr, s3 = nullptr;
    static cudaEvent_t evFork = nullptr, evCsr = nullptr, evCsr3 = nullptr;
    static cudaEvent_t evScore = nullptr, evJoin = nullptr;
    if (s2 == nullptr) {
        cudaStreamCreateWithFlags(&s2, cudaStreamNonBlocking);
        cudaStreamCreateWithFlags(&s3, cudaStreamNonBlocking);
        cudaEventCreateWithFlags(&evFork,  cudaEventDisableTiming);
        cudaEventCreateWithFlags(&evCsr,   cudaEventDisableTiming);
        cudaEventCreateWithFlags(&evCsr3,  cudaEventDisableTiming);
        cudaEventCreateWithFlags(&evScore, cudaEventDisableTiming);
        cudaEventCreateWithFlags(&evJoin,  cudaEventDisableTiming);
    }
    cudaStream_t s0 = 0;

    // ---- fork: graph-0 CSR on s2, graph-1 CSR on s3, FC/projection on s0 ----
    cudaEventRecord(evFork, s0);
    cudaStreamWaitEvent(s2, evFork, 0);
    cudaStreamWaitEvent(s3, evFork, 0);

    // graph 0 CSR chain (s2) — counts reused as 'partial' after count (separate halves):
    zero_k<<<NB, TPB, 0, s2>>>(counts[0], NTOT);
    count_k<<<EB, TPB, 0, s2>>>(dsts[0], counts[0]);
    scanA_k<<<SCAN_NB, SCAN_B, 0, s2>>>(counts[0], cursor[0], bsums[0]);  // partial->cursor tmp
    scanB_k<<<1, 256, 0, s2>>>(bsums[0]);
    scanC_k<<<SCAN_NB, SCAN_B, 0, s2>>>(cursor[0], bsums[0], rowptr[0], cursor[0]);
    scatter_k<<<EB, TPB, 0, s2>>>(srcs[0], dsts[0], cursor[0], csrsrc[0]);
    pack_w2_k<<<64, 256, 0, s2>>>(W2, res2, w2pack);
    cudaEventRecord(evCsr, s2);

    // graph 1 CSR chain (s3):
    zero_k<<<NB, TPB, 0, s3>>>(counts[1], NTOT);
    count_k<<<EB, TPB, 0, s3>>>(dsts[1], counts[1]);
    scanA_k<<<SCAN_NB, SCAN_B, 0, s3>>>(counts[1], cursor[1], bsums[1]);
    scanB_k<<<1, 256, 0, s3>>>(bsums[1]);
    scanC_k<<<SCAN_NB, SCAN_B, 0, s3>>>(cursor[1], bsums[1], rowptr[1], cursor[1]);
    scatter_k<<<EB, TPB, 0, s3>>>(srcs[1], dsts[1], cursor[1], csrsrc[1]);
    cudaEventRecord(evCsr3, s3);

    // main chain (s0)
    gemm64<<<dim3(1, (NTYPE0 + 63) / 64), TPB, 0, s0>>>(features0, fc_w0, fc_b0, h,
                                                        NTYPE0, 128, 64);
    gemm64<<<dim3(1, (N1n + 63) / 64), TPB, 0, s0>>>(features1, fc_w1, fc_b1,
                                                     h + (size_t)NTYPE0 * 64,
                                                     N1n, 128, 64);
    gemm128<<<dim3(2, MB, 2), 256, 0, s0>>>(h, W0, featb, NTOT, 64, 256,
                                            (long long)64 * 256, (long long)NPAD * 256);

    // join CSR into main before softmax/aggregation use; s2 also needs CSR1 later
    cudaStreamWaitEvent(s0, evCsr, 0);
    cudaStreamWaitEvent(s0, evCsr3, 0);
    cudaStreamWaitEvent(s2, evCsr3, 0);

    float* cur = h;
    float* nxt = acc;
    for (int l = 0; l < 2; l++) {
        int Kin = (l == 0) ? 64 : 256;
        const float* Wl  = (l == 0) ? W0 : W1;
        const float* all = (l == 0) ? al0 : al1;
        const float* arl = (l == 0) ? ar0 : ar1;
        const float* bl  = (l == 0) ? b0 : b1;
        if (l != 0)
            gemm128<<<dim3(2, MB, 2), 256, 0, s0>>>(cur, Wl, featb, NTOT, Kin, 256,
                                                    (long long)Kin * 256,
                                                    (long long)NPAD * 256);

        // fork the whole graph-1 edge pipeline (scores+softmax) to s2
        cudaEventRecord(evScore, s0);
        cudaStreamWaitEvent(s2, evScore, 0);
        scores_k<<<NTOT, 128, 0, s0>>>(feat[0], 256, all, arl, el[0], er[0], 4, 64);
        softmax_k<4><<<(NTOT + 7) / 8, 256, 0, s0>>>(rowptr[0], csrsrc[0], el[0], er[0], alpha[0]);
        scores_k<<<NTOT, 128, 0, s2>>>(feat[1], 256, all + 256, arl + 256, el[1], er[1], 4, 64);
        softmax_k<4><<<(NTOT + 7) / 8, 256, 0, s2>>>(rowptr[1], csrsrc[1], el[1], er[1], alpha[1]);
        cudaEventRecord(evJoin, s2);
        cudaStreamWaitEvent(s0, evJoin, 0);

        aggr256_k<<<NTOT, 256, 0, s0>>>(rowptr[0], csrsrc[0], alpha[0], feat[0],
                                        rowptr[1], csrsrc[1], alpha[1], feat[1],
                                        cur, bl, bl + 256, mix_w, l, (l == 1) ? 1 : 0, nxt);
        float* t = cur; cur = nxt; nxt = t;
    }

    // ---- layer 2 (H=1, D=16): single packed N=64 GEMM, softmax, aggregate ----
    gemm64<<<dim3(1, (NTOT + 63) / 64), TPB, 0, s0>>>(cur, w2pack, nullptr, l2out, NTOT, 256, 64);

    cudaEventRecord(evScore, s0);
    cudaStreamWaitEvent(s2, evScore, 0);
    scores_k<<<NTOT, 32, 0, s0>>>(l2out, 64, al2, ar2, el[0], er[0], 1, 16);
    softmax_k<1><<<(NTOT + 7) / 8, 256, 0, s0>>>(rowptr[0], csrsrc[0], el[0], er[0], alpha[0]);
    scores_k<<<NTOT, 32, 0, s2>>>(l2out + 16, 64, al2 + 16, ar2 + 16, el[1], er[1], 1, 16);
    softmax_k<1><<<(NTOT + 7) / 8, 256, 0, s2>>>(rowptr[1], csrsrc[1], el[1], er[1], alpha[1]);
    cudaEventRecord(evJoin, s2);
    cudaStreamWaitEvent(s0, evJoin, 0);

    aggr16_k<<<(NTOT + 15) / 16, 256, 0, s0>>>(rowptr[0], csrsrc[0], alpha[0],
                                               rowptr[1], csrsrc[1], alpha[1],
                                               l2out, b2, mix_w, (float*)d_out);
}

// round 16
// speedup vs baseline: 1.4533x; 1.1058x over previous
#include <cuda_runtime.h>
#include <math.h>

#define NTOT   50000
#define NTYPE0 30000
#define ETOT   400000
#define NPAD   50048
#define SCAN_B 256
#define SCAN_NB ((NTOT + SCAN_B - 1) / SCAN_B)   // 196

// ---------------- static scratch ----------------
__device__ float g_h[NPAD * 256];
__device__ float g_acc[NPAD * 256];
__device__ float g_feat[2 * NPAD * 256];
__device__ float g_l2out[NPAD * 64];
__device__ float g_w2pack[256 * 64];
__device__ float g_el[2][NTOT * 4];
__device__ float g_er[2][NTOT * 4];
__device__ float g_alpha[2][ETOT * 4];
__device__ int   g_rowptr[2][NTOT + 1];
__device__ int   g_cursor[2][NTOT];
__device__ int   g_counts[2][NTOT];
__device__ int   g_bsums[2][SCAN_NB + 1];
__device__ int   g_csrsrc[2][ETOT];

// ---------------- packed f32x2 helpers (FFMA2: 2x fp32 FMA rate on sm_103a) --------
__device__ __forceinline__ unsigned long long pack2(float x, float y) {
    unsigned long long r;
    asm("mov.b64 %0, {%1, %2};" : "=l"(r) : "f"(x), "f"(y));
    return r;
}
__device__ __forceinline__ void ffma2(unsigned long long& d, unsigned long long a,
                                      unsigned long long b) {
    asm("fma.rn.f32x2 %0, %1, %2, %3;" : "=l"(d) : "l"(a), "l"(b), "l"(d));
}
__device__ __forceinline__ float2 unpack2(unsigned long long v) {
    float2 r;
    asm("mov.b64 {%0, %1}, %2;" : "=f"(r.x), "=f"(r.y) : "l"(v));
    return r;
}

// ---------------- CSR build ----------------
__global__ void zero_k(int* __restrict__ c, int count)
{
    int t = blockIdx.x * blockDim.x + threadIdx.x;
    if (t < count) c[t] = 0;
}

__global__ void count_k(const int* __restrict__ dst, int* __restrict__ counts)
{
    int e = blockIdx.x * blockDim.x + threadIdx.x;
    if (e < ETOT) atomicAdd(&counts[dst[e]], 1);
}

__global__ void scanA_k(const int* __restrict__ counts, int* __restrict__ partial,
                        int* __restrict__ bsums)
{
    __shared__ int wsum[8];
    int b = blockIdx.x;
    int tid = threadIdx.x, lane = tid & 31, wid = tid >> 5;
    int i = b * SCAN_B + tid;
    int v = (i < NTOT) ? counts[i] : 0;
    int x = v;
#pragma unroll
    for (int o = 1; o < 32; o <<= 1) {
        int y = __shfl_up_sync(~0u, x, o);
        if (lane >= o) x += y;
    }
    if (lane == 31) wsum[wid] = x;
    __syncthreads();
    if (wid == 0 && lane < 8) {
        int s = wsum[lane];
#pragma unroll
        for (int o = 1; o < 8; o <<= 1) {
            int y = __shfl_up_sync(0xFF, s, o);
            if (lane >= o) s += y;
        }
        wsum[lane] = s;
    }
    __syncthreads();
    int woff = (wid == 0) ? 0 : wsum[wid - 1];
    int excl = x - v + woff;
    if (i < NTOT) partial[i] = excl;
    if (tid == SCAN_B - 1) bsums[b] = excl + v;
}

__global__ void scanB_k(int* __restrict__ bsums)
{
    __shared__ int wsum[8];
    int tid = threadIdx.x, lane = tid & 31, wid = tid >> 5;
    int v = (tid < SCAN_NB) ? bsums[tid] : 0;
    int x = v;
#pragma unroll
    for (int o = 1; o < 32; o <<= 1) {
        int y = __shfl_up_sync(~0u, x, o);
        if (lane >= o) x += y;
    }
    if (lane == 31) wsum[wid] = x;
    __syncthreads();
    if (wid == 0 && lane < 8) {
        int s = wsum[lane];
#pragma unroll
        for (int o = 1; o < 8; o <<= 1) {
            int y = __shfl_up_sync(0xFF, s, o);
            if (lane >= o) s += y;
        }
        wsum[lane] = s;
    }
    __syncthreads();
    int woff = (wid == 0) ? 0 : wsum[wid - 1];
    int excl = x - v + woff;
    if (tid < SCAN_NB) bsums[tid] = excl;
    if (tid == SCAN_NB - 1) bsums[SCAN_NB] = excl + v;
}

__global__ void scanC_k(const int* __restrict__ partial, const int* __restrict__ bsums,
                        int* __restrict__ rowptr, int* __restrict__ cursor)
{
    int b = blockIdx.x;
    int i = b * SCAN_B + threadIdx.x;
    if (i < NTOT) {
        int v = partial[i] + bsums[b];
        rowptr[i] = v;
        cursor[i] = v;
    }
    if (i == 0) rowptr[NTOT] = bsums[SCAN_NB];
}

__global__ void scatter_k(const int* __restrict__ src, const int* __restrict__ dst,
                          int* __restrict__ cursor, int* __restrict__ csrsrc)
{
    int e = blockIdx.x * blockDim.x + threadIdx.x;
    if (e >= ETOT) return;
    int pos = atomicAdd(&cursor[dst[e]], 1);
    csrsrc[pos] = src[e];
}

// ---------------- 64x64 tile fp32 GEMM with FFMA2 (small-N cases) ----------------
__global__ void gemm64(const float* __restrict__ A, const float* __restrict__ B,
                       const float* __restrict__ bias, float* __restrict__ C,
                       int M, int K, int N)
{
    __shared__ float As[16][65];
    __shared__ float Bs[16][64];
    int tid = threadIdx.x;
    int rowBase = blockIdx.y * 64;
    int colBase = blockIdx.x * 64;
    int tx = tid & 15, ty = tid >> 4;
    int arow = tid >> 2, acol = (tid & 3) << 2;
    int brow = tid >> 4, bcol = (tid & 15) << 2;

    unsigned long long acc[4][2];
#pragma unroll
    for (int i = 0; i < 4; i++) { acc[i][0] = 0ull; acc[i][1] = 0ull; }

    for (int k0 = 0; k0 < K; k0 += 16) {
        float4 av = make_float4(0.f, 0.f, 0.f, 0.f);
        if (rowBase + arow < M)
            av = *reinterpret_cast<const float4*>(A + (size_t)(rowBase + arow) * K + k0 + acol);
        As[acol + 0][arow] = av.x; As[acol + 1][arow] = av.y;
        As[acol + 2][arow] = av.z; As[acol + 3][arow] = av.w;
        float4 bv = make_float4(0.f, 0.f, 0.f, 0.f);
        if (colBase + bcol < N)
            bv = *reinterpret_cast<const float4*>(B + (size_t)(k0 + brow) * N + colBase + bcol);
        *reinterpret_cast<float4*>(&Bs[brow][bcol]) = bv;
        __syncthreads();
#pragma unroll
        for (int k = 0; k < 16; k++) {
            float a0 = As[k][(ty << 2) + 0], a1 = As[k][(ty << 2) + 1];
            float a2 = As[k][(ty << 2) + 2], a3 = As[k][(ty << 2) + 3];
            unsigned long long b01 = *reinterpret_cast<const unsigned long long*>(&Bs[k][(tx << 2) + 0]);
            unsigned long long b23 = *reinterpret_cast<const unsigned long long*>(&Bs[k][(tx << 2) + 2]);
            unsigned long long p0 = pack2(a0, a0), p1 = pack2(a1, a1);
            unsigned long long p2 = pack2(a2, a2), p3 = pack2(a3, a3);
            ffma2(acc[0][0], p0, b01); ffma2(acc[0][1], p0, b23);
            ffma2(acc[1][0], p1, b01); ffma2(acc[1][1], p1, b23);
            ffma2(acc[2][0], p2, b01); ffma2(acc[2][1], p2, b23);
            ffma2(acc[3][0], p3, b01); ffma2(acc[3][1], p3, b23);
        }
        __syncthreads();
    }
#pragma unroll
    for (int i = 0; i < 4; i++) {
        int r = rowBase + (ty << 2) + i;
        if (r >= M) continue;
        float2 u0 = unpack2(acc[i][0]);
        float2 u1 = unpack2(acc[i][1]);
        float vals[4] = {u0.x, u0.y, u1.x, u1.y};
#pragma unroll
        for (int j = 0; j < 4; j++) {
            int c = colBase + (tx << 2) + j;
            if (c < N) C[(size_t)r * N + c] = vals[j] + (bias ? bias[c] : 0.f);
        }
    }
}

// ---------------- 128x128 tile fp32 GEMM (R4 shape) + fused attention scores -------
// N == 256. Block owns heads {cb/64, cb/64+1} for its 128 rows; el/er computed
// from fp32 accumulators via 16-lane shfl reduce (deletes scores_k re-reads).
__global__ void __launch_bounds__(256, 2)
gemm128s(const float* __restrict__ A, const float* __restrict__ B,
         float* __restrict__ C, int M, int K, int N,
         long long bStride, long long cStride,
         const float* __restrict__ al, const float* __restrict__ ar,
         float* __restrict__ elb, float* __restrict__ erb)
{
    __shared__ float As[8][132];
    __shared__ float Bs[8][128];
    const float* Bp = B + (long long)blockIdx.z * bStride;
    float* Cp = C + (long long)blockIdx.z * cStride;

    int tid = threadIdx.x;
    int rb = blockIdx.y * 128, cb = blockIdx.x * 128;
    int tx = tid & 15, ty = tid >> 4;
    int arow = tid >> 1, acol = (tid & 1) << 2;
    int brow = tid >> 5, bcol = (tid & 31) << 2;

    unsigned long long acc[8][4];
#pragma unroll
    for (int i = 0; i < 8; i++)
#pragma unroll
        for (int j = 0; j < 4; j++) acc[i][j] = 0ull;

    for (int k0 = 0; k0 < K; k0 += 8) {
        float4 av = make_float4(0.f, 0.f, 0.f, 0.f);
        if (rb + arow < M)
            av = *reinterpret_cast<const float4*>(A + (size_t)(rb + arow) * K + k0 + acol);
        As[acol + 0][arow] = av.x; As[acol + 1][arow] = av.y;
        As[acol + 2][arow] = av.z; As[acol + 3][arow] = av.w;
        float4 bv = *reinterpret_cast<const float4*>(Bp + (size_t)(k0 + brow) * N + cb + bcol);
        *reinterpret_cast<float4*>(&Bs[brow][bcol]) = bv;
        __syncthreads();
#pragma unroll
        for (int k = 0; k < 8; k++) {
            float a[8];
            *reinterpret_cast<float4*>(a)     = *reinterpret_cast<float4*>(&As[k][ty * 8]);
            *reinterpret_cast<float4*>(a + 4) = *reinterpret_cast<float4*>(&As[k][ty * 8 + 4]);
            unsigned long long b2[4];
            b2[0] = *reinterpret_cast<const unsigned long long*>(&Bs[k][tx * 4]);
            b2[1] = *reinterpret_cast<const unsigned long long*>(&Bs[k][tx * 4 + 2]);
            b2[2] = *reinterpret_cast<const unsigned long long*>(&Bs[k][64 + tx * 4]);
            b2[3] = *reinterpret_cast<const unsigned long long*>(&Bs[k][64 + tx * 4 + 2]);
#pragma unroll
            for (int i = 0; i < 8; i++) {
                unsigned long long aa = pack2(a[i], a[i]);
                ffma2(acc[i][0], aa, b2[0]);
                ffma2(acc[i][1], aa, b2[1]);
                ffma2(acc[i][2], aa, b2[2]);
                ffma2(acc[i][3], aa, b2[3]);
            }
        }
        __syncthreads();
    }

    const float* alg = al + (size_t)blockIdx.z * 256;
    const float* arg = ar + (size_t)blockIdx.z * 256;
    float* elg = elb + (size_t)blockIdx.z * (NTOT * 4);
    float* erg = erb + (size_t)blockIdx.z * (NTOT * 4);
    int hbase = cb >> 6;
    float alv0[4], arv0[4], alv1[4], arv1[4];
#pragma unroll
    for (int j = 0; j < 4; j++) {
        alv0[j] = alg[cb + tx * 4 + j];       arv0[j] = arg[cb + tx * 4 + j];
        alv1[j] = alg[cb + 64 + tx * 4 + j];  arv1[j] = arg[cb + 64 + tx * 4 + j];
    }

#pragma unroll
    for (int i = 0; i < 8; i++) {
        int r = rb + ty * 8 + i;
        float2 u0 = unpack2(acc[i][0]), u1 = unpack2(acc[i][1]);
        float2 u2 = unpack2(acc[i][2]), u3 = unpack2(acc[i][3]);
        float v[8] = {u0.x, u0.y, u1.x, u1.y, u2.x, u2.y, u3.x, u3.y};
        *reinterpret_cast<float4*>(Cp + (size_t)r * N + cb + tx * 4)      = *reinterpret_cast<float4*>(v);
        *reinterpret_cast<float4*>(Cp + (size_t)r * N + cb + 64 + tx * 4) = *reinterpret_cast<float4*>(v + 4);

        float se0 = 0.f, sr0 = 0.f, se1 = 0.f, sr1 = 0.f;
#pragma unroll
        for (int j = 0; j < 4; j++) {
            se0 += v[j] * alv0[j];     sr0 += v[j] * arv0[j];
            se1 += v[4 + j] * alv1[j]; sr1 += v[4 + j] * arv1[j];
        }
#pragma unroll
        for (int o = 8; o > 0; o >>= 1) {
            se0 += __shfl_down_sync(~0u, se0, o, 16);
            sr0 += __shfl_down_sync(~0u, sr0, o, 16);
            se1 += __shfl_down_sync(~0u, se1, o, 16);
            sr1 += __shfl_down_sync(~0u, sr1, o, 16);
        }
        if (tx == 0 && r < NTOT) {
            elg[r * 4 + hbase]     = se0;
            erg[r * 4 + hbase]     = sr0;
            elg[r * 4 + hbase + 1] = se1;
            erg[r * 4 + hbase + 1] = sr1;
        }
    }
}

// ---------------- pack layer-2 weights ----------------
__global__ void pack_w2_k(const float* __restrict__ W2, const float* __restrict__ res2,
                          float* __restrict__ out)
{
    int idx = blockIdx.x * blockDim.x + threadIdx.x;
    if (idx >= 256 * 64) return;
    int k = idx >> 6, d = idx & 63;
    int g = (d >> 4) & 1;
    int which = d >> 5;
    int dd = d & 15;
    const float* src = which == 0 ? W2 : res2;
    out[idx] = src[(size_t)g * 256 * 16 + k * 16 + dd];
}

// ---------------- attention scores (layer 2 only): warp per (node, head) -----------
__global__ void scores_k(const float* __restrict__ feat, int stride,
                         const float* __restrict__ al, const float* __restrict__ ar,
                         float* __restrict__ el, float* __restrict__ er, int H, int D)
{
    int n = blockIdx.x;
    int wid = threadIdx.x >> 5;
    int lane = threadIdx.x & 31;
    const float* f = feat + (size_t)n * stride + wid * D;
    float sl = 0.f, sr = 0.f;
    for (int d = lane; d < D; d += 32) {
        float v = f[d];
        sl += v * al[wid * D + d];
        sr += v * ar[wid * D + d];
    }
#pragma unroll
    for (int o = 16; o > 0; o >>= 1) {
        sl += __shfl_down_sync(~0u, sl, o);
        sr += __shfl_down_sync(~0u, sr, o);
    }
    if (lane == 0) { el[n * H + wid] = sl; er[n * H + wid] = sr; }
}

// ---------------- edge softmax (CSR, warp per dst node) — R4 exact form ------------
template <int H>
__global__ void softmax_k(const int* __restrict__ rowptr, const int* __restrict__ csrsrc,
                          const float* __restrict__ el, const float* __restrict__ er,
                          float* __restrict__ alpha)
{
    int n = blockIdx.x * (blockDim.x >> 5) + (threadIdx.x >> 5);
    int lane = threadIdx.x & 31;
    if (n >= NTOT) return;
    int beg = rowptr[n], end = rowptr[n + 1];
    if (beg == end) return;

    float erh[H];
#pragma unroll
    for (int h = 0; h < H; h++) erh[h] = er[n * H + h];

    float mx[H];
#pragma unroll
    for (int h = 0; h < H; h++) mx[h] = -1e30f;

    for (int p = beg + lane; p < end; p += 32) {
        int s = csrsrc[p];
#pragma unroll
        for (int h = 0; h < H; h++) {
            float e = el[s * H + h] + erh[h];
            e = e > 0.f ? e : 0.2f * e;
            alpha[p * H + h] = e;
            mx[h] = fmaxf(mx[h], e);
        }
    }
#pragma unroll
    for (int h = 0; h < H; h++)
#pragma unroll
        for (int o = 16; o > 0; o >>= 1)
            mx[h] = fmaxf(mx[h], __shfl_xor_sync(~0u, mx[h], o));

    float den[H];
#pragma unroll
    for (int h = 0; h < H; h++) den[h] = 0.f;
    for (int p = beg + lane; p < end; p += 32) {
#pragma unroll
        for (int h = 0; h < H; h++) {
            float x = expf(alpha[p * H + h] - mx[h]);
            alpha[p * H + h] = x;
            den[h] += x;
        }
    }
#pragma unroll
    for (int h = 0; h < H; h++)
#pragma unroll
        for (int o = 16; o > 0; o >>= 1)
            den[h] += __shfl_xor_sync(~0u, den[h], o);

    float inv[H];
#pragma unroll
    for (int h = 0; h < H; h++) inv[h] = 1.f / den[h];
    for (int p = beg + lane; p < end; p += 32) {
#pragma unroll
        for (int h = 0; h < H; h++) alpha[p * H + h] *= inv[h];
    }
}

// ---------------- fused dual-graph aggregation + epilogue (HD=256) — R4 exact ------
__global__ void aggr256_k(const int* __restrict__ rp0, const int* __restrict__ cs0,
                          const float* __restrict__ a0, const float* __restrict__ f0,
                          const int* __restrict__ rp1, const int* __restrict__ cs1,
                          const float* __restrict__ a1, const float* __restrict__ f1,
                          const float* __restrict__ h, const float* __restrict__ bias0,
                          const float* __restrict__ bias1, const float* __restrict__ mixw,
                          int layer, int useRes, float* __restrict__ out)
{
    int n = blockIdx.x;
    int d = threadIdx.x;
    int head = d >> 6;

    float acc0 = 0.f, acc1 = 0.f;
    {
        int p = rp0[n], e = rp0[n + 1];
        for (; p + 2 <= e; p += 2) {
            int s0 = __ldg(&cs0[p]),     s1 = __ldg(&cs0[p + 1]);
            float w0 = __ldg(&a0[p * 4 + head]);
            float w1 = __ldg(&a0[(p + 1) * 4 + head]);
            float v0 = f0[(size_t)s0 * 256 + d];
            float v1 = f0[(size_t)s1 * 256 + d];
            acc0 += v0 * w0 + v1 * w1;
        }
        if (p < e) {
            int s = __ldg(&cs0[p]);
            acc0 += f0[(size_t)s * 256 + d] * __ldg(&a0[p * 4 + head]);
        }
    }
    {
        int p = rp1[n], e = rp1[n + 1];
        for (; p + 2 <= e; p += 2) {
            int s0 = __ldg(&cs1[p]),     s1 = __ldg(&cs1[p + 1]);
            float w0 = __ldg(&a1[p * 4 + head]);
            float w1 = __ldg(&a1[(p + 1) * 4 + head]);
            float v0 = f1[(size_t)s0 * 256 + d];
            float v1 = f1[(size_t)s1 * 256 + d];
            acc1 += v0 * w0 + v1 * w1;
        }
        if (p < e) {
            int s = __ldg(&cs1[p]);
            acc1 += f1[(size_t)s * 256 + d] * __ldg(&a1[p * 4 + head]);
        }
    }

    float res = useRes ? h[(size_t)n * 256 + d] : 0.f;
    float v0 = acc0 + res + bias0[d];
    float v1 = acc1 + res + bias1[d];
    v0 = v0 > 0.f ? v0 : expm1f(v0);
    v1 = v1 > 0.f ? v1 : expm1f(v1);

    int ty = (n < NTYPE0) ? 0 : 1;
    float m0 = mixw[ty * 6 + layer * 2 + 0];
    float m1 = mixw[ty * 6 + layer * 2 + 1];
    float mxw = fmaxf(m0, m1);
    float e0 = expf(m0 - mxw), e1 = expf(m1 - mxw);
    float inv = 1.f / (e0 + e1);
    out[(size_t)n * 256 + d] = v0 * (e0 * inv) + v1 * (e1 * inv);
}

// ---------------- layer 2 aggregation (H=1, D=16), packed l2 buffer — R4 exact -----
__global__ void aggr16_k(const int* __restrict__ rp0, const int* __restrict__ cs0,
                         const float* __restrict__ a0,
                         const int* __restrict__ rp1, const int* __restrict__ cs1,
                         const float* __restrict__ a1,
                         const float* __restrict__ l2, const float* __restrict__ b2,
                         const float* __restrict__ mixw, float* __restrict__ logits)
{
    int n = blockIdx.x * 16 + (threadIdx.x >> 4);
    int d = threadIdx.x & 15;
    if (n >= NTOT) return;

    float acc0 = 0.f, acc1 = 0.f;
    int b = rp0[n], e = rp0[n + 1];
    for (int p = b; p < e; p++)
        acc0 += l2[(size_t)__ldg(&cs0[p]) * 64 + d] * __ldg(&a0[p]);
    b = rp1[n]; e = rp1[n + 1];
    for (int p = b; p < e; p++)
        acc1 += l2[(size_t)__ldg(&cs1[p]) * 64 + 16 + d] * __ldg(&a1[p]);

    float v0 = acc0 + l2[(size_t)n * 64 + 32 + d] + b2[d];
    float v1 = acc1 + l2[(size_t)n * 64 + 48 + d] + b2[16 + d];

    int ty = (n < NTYPE0) ? 0 : 1;
    float m0 = mixw[ty * 6 + 4 + 0];
    float m1 = mixw[ty * 6 + 4 + 1];
    float mxw = fmaxf(m0, m1);
    float e0 = expf(m0 - mxw), e1 = expf(m1 - mxw);
    float inv = 1.f / (e0 + e1);
    logits[(size_t)n * 16 + d] = v0 * (e0 * inv) + v1 * (e1 * inv);
}

// ---------------- host orchestration (tri-stream fork/join) ----------------
extern "C" void kernel_launch(void* const* d_in, const int* in_sizes, int n_in,
                              void* d_out, int out_size)
{
    const float* features0 = (const float*)d_in[0];
    const float* features1 = (const float*)d_in[1];
    const float* fc_w0 = (const float*)d_in[2];
    const float* fc_b0 = (const float*)d_in[3];
    const float* fc_w1 = (const float*)d_in[4];
    const float* fc_b1 = (const float*)d_in[5];
    const float* mix_w = (const float*)d_in[6];
    const float* W0  = (const float*)d_in[7];
    const float* al0 = (const float*)d_in[8];
    const float* ar0 = (const float*)d_in[9];
    const float* b0  = (const float*)d_in[10];
    const float* W1  = (const float*)d_in[11];
    const float* al1 = (const float*)d_in[12];
    const float* ar1 = (const float*)d_in[13];
    const float* b1  = (const float*)d_in[14];
    const float* W2  = (const float*)d_in[15];
    const float* al2 = (const float*)d_in[16];
    const float* ar2 = (const float*)d_in[17];
    const float* b2  = (const float*)d_in[18];
    const float* res2= (const float*)d_in[19];
    const int* srcs[2] = {(const int*)d_in[20], (const int*)d_in[22]};
    const int* dsts[2] = {(const int*)d_in[21], (const int*)d_in[23]};

    float *h, *acc, *featb, *l2out, *w2pack, *elp, *erp, *alphap;
    int *rowptrp, *cursorp, *countsp, *bsumsp, *csrsrcp;
    cudaGetSymbolAddress((void**)&h,      g_h);
    cudaGetSymbolAddress((void**)&acc,    g_acc);
    cudaGetSymbolAddress((void**)&featb,  g_feat);
    cudaGetSymbolAddress((void**)&l2out,  g_l2out);
    cudaGetSymbolAddress((void**)&w2pack, g_w2pack);
    cudaGetSymbolAddress((void**)&elp,    g_el);
    cudaGetSymbolAddress((void**)&erp,    g_er);
    cudaGetSymbolAddress((void**)&alphap, g_alpha);
    cudaGetSymbolAddress((void**)&rowptrp, g_rowptr);
    cudaGetSymbolAddress((void**)&cursorp, g_cursor);
    cudaGetSymbolAddress((void**)&countsp, g_counts);
    cudaGetSymbolAddress((void**)&bsumsp,  g_bsums);
    cudaGetSymbolAddress((void**)&csrsrcp, g_csrsrc);

    float* feat[2]  = {featb, featb + (size_t)NPAD * 256};
    float* el[2]    = {elp, elp + NTOT * 4};
    float* er[2]    = {erp, erp + NTOT * 4};
    float* alpha[2] = {alphap, alphap + ETOT * 4};
    int* rowptr[2]  = {rowptrp, rowptrp + NTOT + 1};
    int* cursor[2]  = {cursorp, cursorp + NTOT};
    int* counts[2]  = {countsp, countsp + NTOT};
    int* bsums[2]   = {bsumsp, bsumsp + SCAN_NB + 1};
    int* csrsrc[2]  = {csrsrcp, csrsrcp + ETOT};

    const int TPB = 256;
    const int N1n = NTOT - NTYPE0;
    const int EB = (ETOT + TPB - 1) / TPB;
    const int MB = (NTOT + 127) / 128;
    const int NB = (NTOT + TPB - 1) / TPB;

    static cudaStream_t s2 = nullptr, s3 = nullptr;
    static cudaEvent_t evFork = nullptr, evCsr = nullptr, evCsr3 = nullptr;
    static cudaEvent_t evScore = nullptr, evJoin = nullptr;
    if (s2 == nullptr) {
        cudaStreamCreateWithFlags(&s2, cudaStreamNonBlocking);
        cudaStreamCreateWithFlags(&s3, cudaStreamNonBlocking);
        cudaEventCreateWithFlags(&evFork,  cudaEventDisableTiming);
        cudaEventCreateWithFlags(&evCsr,   cudaEventDisableTiming);
        cudaEventCreateWithFlags(&evCsr3,  cudaEventDisableTiming);
        cudaEventCreateWithFlags(&evScore, cudaEventDisableTiming);
        cudaEventCreateWithFlags(&evJoin,  cudaEventDisableTiming);
    }
    cudaStream_t s0 = 0;

    // ---- fork: graph-0 CSR on s2, graph-1 CSR on s3, FC/projection on s0 ----
    cudaEventRecord(evFork, s0);
    cudaStreamWaitEvent(s2, evFork, 0);
    cudaStreamWaitEvent(s3, evFork, 0);

    zero_k<<<NB, TPB, 0, s2>>>(counts[0], NTOT);
    count_k<<<EB, TPB, 0, s2>>>(dsts[0], counts[0]);
    scanA_k<<<SCAN_NB, SCAN_B, 0, s2>>>(counts[0], cursor[0], bsums[0]);
    scanB_k<<<1, 256, 0, s2>>>(bsums[0]);
    scanC_k<<<SCAN_NB, SCAN_B, 0, s2>>>(cursor[0], bsums[0], rowptr[0], cursor[0]);
    scatter_k<<<EB, TPB, 0, s2>>>(srcs[0], dsts[0], cursor[0], csrsrc[0]);
    pack_w2_k<<<64, 256, 0, s2>>>(W2, res2, w2pack);
    cudaEventRecord(evCsr, s2);

    zero_k<<<NB, TPB, 0, s3>>>(counts[1], NTOT);
    count_k<<<EB, TPB, 0, s3>>>(dsts[1], counts[1]);
    scanA_k<<<SCAN_NB, SCAN_B, 0, s3>>>(counts[1], cursor[1], bsums[1]);
    scanB_k<<<1, 256, 0, s3>>>(bsums[1]);
    scanC_k<<<SCAN_NB, SCAN_B, 0, s3>>>(cursor[1], bsums[1], rowptr[1], cursor[1]);
    scatter_k<<<EB, TPB, 0, s3>>>(srcs[1], dsts[1], cursor[1], csrsrc[1]);
    cudaEventRecord(evCsr3, s3);

    // main chain (s0): FC -> fused projection+scores for layer 0
    gemm64<<<dim3(1, (NTYPE0 + 63) / 64), TPB, 0, s0>>>(features0, fc_w0, fc_b0, h,
                                                        NTYPE0, 128, 64);
    gemm64<<<dim3(1, (N1n + 63) / 64), TPB, 0, s0>>>(features1, fc_w1, fc_b1,
                                                     h + (size_t)NTYPE0 * 64,
                                                     N1n, 128, 64);
    gemm128s<<<dim3(2, MB, 2), 256, 0, s0>>>(h, W0, featb, NTOT, 64, 256,
                                             (long long)64 * 256, (long long)NPAD * 256,
                                             al0, ar0, elp, erp);

    cudaStreamWaitEvent(s0, evCsr, 0);
    cudaStreamWaitEvent(s0, evCsr3, 0);
    cudaStreamWaitEvent(s2, evCsr3, 0);

    float* cur = h;
    float* nxt = acc;
    for (int l = 0; l < 2; l++) {
        const float* bl = (l == 0) ? b0 : b1;
        if (l != 0)
            gemm128s<<<dim3(2, MB, 2), 256, 0, s0>>>(cur, W1, featb, NTOT, 256, 256,
                                                     (long long)256 * 256,
                                                     (long long)NPAD * 256,
                                                     al1, ar1, elp, erp);

        // graph-1 softmax on s2 concurrently with graph-0 softmax on s0
        cudaEventRecord(evScore, s0);
        cudaStreamWaitEvent(s2, evScore, 0);
        softmax_k<4><<<(NTOT + 7) / 8, 256, 0, s0>>>(rowptr[0], csrsrc[0], el[0], er[0], alpha[0]);
        softmax_k<4><<<(NTOT + 7) / 8, 256, 0, s2>>>(rowptr[1], csrsrc[1], el[1], er[1], alpha[1]);
        cudaEventRecord(evJoin, s2);
        cudaStreamWaitEvent(s0, evJoin, 0);

        aggr256_k<<<NTOT, 256, 0, s0>>>(rowptr[0], csrsrc[0], alpha[0], feat[0],
                                        rowptr[1], csrsrc[1], alpha[1], feat[1],
                                        cur, bl, bl + 256, mix_w, l, (l == 1) ? 1 : 0, nxt);
        float* t = cur; cur = nxt; nxt = t;
    }

    // ---- layer 2 (H=1, D=16): single packed N=64 GEMM, scores, softmax, aggregate --
    gemm64<<<dim3(1, (NTOT + 63) / 64), TPB, 0, s0>>>(cur, w2pack, nullptr, l2out, NTOT, 256, 64);

    cudaEventRecord(evScore, s0);
    cudaStreamWaitEvent(s2, evScore, 0);
    scores_k<<<NTOT, 32, 0, s0>>>(l2out, 64, al2, ar2, el[0], er[0], 1, 16);
    softmax_k<1><<<(NTOT + 7) / 8, 256, 0, s0>>>(rowptr[0], csrsrc[0], el[0], er[0], alpha[0]);
    scores_k<<<NTOT, 32, 0, s2>>>(l2out + 16, 64, al2 + 16, ar2 + 16, el[1], er[1], 1, 16);
    softmax_k<1><<<(NTOT + 7) / 8, 256, 0, s2>>>(rowptr[1], csrsrc[1], el[1], er[1], alpha[1]);
    cudaEventRecord(evJoin, s2);
    cudaStreamWaitEvent(s0, evJoin, 0);

    aggr16_k<<<(NTOT + 15) / 16, 256, 0, s0>>>(rowptr[0], csrsrc[0], alpha[0],
                                               rowptr[1], csrsrc[1], alpha[1],
                                               l2out, b2, mix_w, (float*)d_out);
}

// round 17
// speedup vs baseline: 1.5946x; 1.0973x over previous
#include <cuda_runtime.h>
#include <math.h>

#define NTOT   50000
#define NTYPE0 30000
#define ETOT   400000
#define NPAD   50048
#define SCAN_B 256
#define SCAN_NB ((NTOT + SCAN_B - 1) / SCAN_B)   // 196

// ---------------- static scratch ----------------
__device__ float g_h[NPAD * 256];
__device__ float g_acc[NPAD * 256];
__device__ float g_feat[2 * NPAD * 256];
__device__ float g_l2out[NPAD * 64];
__device__ float g_w2pack[256 * 64];
__device__ float g_el[2][NTOT * 4];
__device__ float g_er[2][NTOT * 4];
__device__ float g_alpha[2][ETOT * 4];
__device__ int   g_rowptr[2][NTOT + 1];
__device__ int   g_cursor[2][NTOT];
__device__ int   g_counts[2][NTOT];
__device__ int   g_bsums[2][SCAN_NB + 1];
__device__ int   g_csrsrc[2][ETOT];

// ---------------- packed f32x2 helpers (FFMA2: 2x fp32 FMA rate on sm_103a) --------
__device__ __forceinline__ unsigned long long pack2(float x, float y) {
    unsigned long long r;
    asm("mov.b64 %0, {%1, %2};" : "=l"(r) : "f"(x), "f"(y));
    return r;
}
__device__ __forceinline__ void ffma2(unsigned long long& d, unsigned long long a,
                                      unsigned long long b) {
    asm("fma.rn.f32x2 %0, %1, %2, %3;" : "=l"(d) : "l"(a), "l"(b), "l"(d));
}
__device__ __forceinline__ float2 unpack2(unsigned long long v) {
    float2 r;
    asm("mov.b64 {%0, %1}, %2;" : "=f"(r.x), "=f"(r.y) : "l"(v));
    return r;
}

// ---------------- CSR build ----------------
__global__ void zero_k(int* __restrict__ c, int count)
{
    int t = blockIdx.x * blockDim.x + threadIdx.x;
    if (t < count) c[t] = 0;
}

__global__ void count_k(const int* __restrict__ dst, int* __restrict__ counts)
{
    int e = blockIdx.x * blockDim.x + threadIdx.x;
    if (e < ETOT) atomicAdd(&counts[dst[e]], 1);
}

__global__ void scanA_k(const int* __restrict__ counts, int* __restrict__ partial,
                        int* __restrict__ bsums)
{
    __shared__ int wsum[8];
    int b = blockIdx.x;
    int tid = threadIdx.x, lane = tid & 31, wid = tid >> 5;
    int i = b * SCAN_B + tid;
    int v = (i < NTOT) ? counts[i] : 0;
    int x = v;
#pragma unroll
    for (int o = 1; o < 32; o <<= 1) {
        int y = __shfl_up_sync(~0u, x, o);
        if (lane >= o) x += y;
    }
    if (lane == 31) wsum[wid] = x;
    __syncthreads();
    if (wid == 0 && lane < 8) {
        int s = wsum[lane];
#pragma unroll
        for (int o = 1; o < 8; o <<= 1) {
            int y = __shfl_up_sync(0xFF, s, o);
            if (lane >= o) s += y;
        }
        wsum[lane] = s;
    }
    __syncthreads();
    int woff = (wid == 0) ? 0 : wsum[wid - 1];
    int excl = x - v + woff;
    if (i < NTOT) partial[i] = excl;
    if (tid == SCAN_B - 1) bsums[b] = excl + v;
}

__global__ void scanB_k(int* __restrict__ bsums)
{
    __shared__ int wsum[8];
    int tid = threadIdx.x, lane = tid & 31, wid = tid >> 5;
    int v = (tid < SCAN_NB) ? bsums[tid] : 0;
    int x = v;
#pragma unroll
    for (int o = 1; o < 32; o <<= 1) {
        int y = __shfl_up_sync(~0u, x, o);
        if (lane >= o) x += y;
    }
    if (lane == 31) wsum[wid] = x;
    __syncthreads();
    if (wid == 0 && lane < 8) {
        int s = wsum[lane];
#pragma unroll
        for (int o = 1; o < 8; o <<= 1) {
            int y = __shfl_up_sync(0xFF, s, o);
            if (lane >= o) s += y;
        }
        wsum[lane] = s;
    }
    __syncthreads();
    int woff = (wid == 0) ? 0 : wsum[wid - 1];
    int excl = x - v + woff;
    if (tid < SCAN_NB) bsums[tid] = excl;
    if (tid == SCAN_NB - 1) bsums[SCAN_NB] = excl + v;
}

__global__ void scanC_k(const int* __restrict__ partial, const int* __restrict__ bsums,
                        int* __restrict__ rowptr, int* __restrict__ cursor)
{
    int b = blockIdx.x;
    int i = b * SCAN_B + threadIdx.x;
    if (i < NTOT) {
        int v = partial[i] + bsums[b];
        rowptr[i] = v;
        cursor[i] = v;
    }
    if (i == 0) rowptr[NTOT] = bsums[SCAN_NB];
}

__global__ void scatter_k(const int* __restrict__ src, const int* __restrict__ dst,
                          int* __restrict__ cursor, int* __restrict__ csrsrc)
{
    int e = blockIdx.x * blockDim.x + threadIdx.x;
    if (e >= ETOT) return;
    int pos = atomicAdd(&cursor[dst[e]], 1);
    csrsrc[pos] = src[e];
}

// ---------------- 64x64 tile fp32 GEMM body (FFMA2) ----------------
__device__ __forceinline__ void gemm64_body(const float* __restrict__ A,
                                            const float* __restrict__ B,
                                            const float* __restrict__ bias,
                                            float* __restrict__ C,
                                            int M, int K, int N, int rowBase, int colBase)
{
    __shared__ float As[16][65];
    __shared__ float Bs[16][64];
    int tid = threadIdx.x;
    int tx = tid & 15, ty = tid >> 4;
    int arow = tid >> 2, acol = (tid & 3) << 2;
    int brow = tid >> 4, bcol = (tid & 15) << 2;

    unsigned long long acc[4][2];
#pragma unroll
    for (int i = 0; i < 4; i++) { acc[i][0] = 0ull; acc[i][1] = 0ull; }

    for (int k0 = 0; k0 < K; k0 += 16) {
        float4 av = make_float4(0.f, 0.f, 0.f, 0.f);
        if (rowBase + arow < M)
            av = *reinterpret_cast<const float4*>(A + (size_t)(rowBase + arow) * K + k0 + acol);
        As[acol + 0][arow] = av.x; As[acol + 1][arow] = av.y;
        As[acol + 2][arow] = av.z; As[acol + 3][arow] = av.w;
        float4 bv = make_float4(0.f, 0.f, 0.f, 0.f);
        if (colBase + bcol < N)
            bv = *reinterpret_cast<const float4*>(B + (size_t)(k0 + brow) * N + colBase + bcol);
        *reinterpret_cast<float4*>(&Bs[brow][bcol]) = bv;
        __syncthreads();
#pragma unroll
        for (int k = 0; k < 16; k++) {
            float a0 = As[k][(ty << 2) + 0], a1 = As[k][(ty << 2) + 1];
            float a2 = As[k][(ty << 2) + 2], a3 = As[k][(ty << 2) + 3];
            unsigned long long b01 = *reinterpret_cast<const unsigned long long*>(&Bs[k][(tx << 2) + 0]);
            unsigned long long b23 = *reinterpret_cast<const unsigned long long*>(&Bs[k][(tx << 2) + 2]);
            unsigned long long p0 = pack2(a0, a0), p1 = pack2(a1, a1);
            unsigned long long p2 = pack2(a2, a2), p3 = pack2(a3, a3);
            ffma2(acc[0][0], p0, b01); ffma2(acc[0][1], p0, b23);
            ffma2(acc[1][0], p1, b01); ffma2(acc[1][1], p1, b23);
            ffma2(acc[2][0], p2, b01); ffma2(acc[2][1], p2, b23);
            ffma2(acc[3][0], p3, b01); ffma2(acc[3][1], p3, b23);
        }
        __syncthreads();
    }
#pragma unroll
    for (int i = 0; i < 4; i++) {
        int r = rowBase + (ty << 2) + i;
        if (r >= M) continue;
        float2 u0 = unpack2(acc[i][0]);
        float2 u1 = unpack2(acc[i][1]);
        float vals[4] = {u0.x, u0.y, u1.x, u1.y};
#pragma unroll
        for (int j = 0; j < 4; j++) {
            int c = colBase + (tx << 2) + j;
            if (c < N) C[(size_t)r * N + c] = vals[j] + (bias ? bias[c] : 0.f);
        }
    }
}

__global__ void gemm64(const float* __restrict__ A, const float* __restrict__ B,
                       const float* __restrict__ bias, float* __restrict__ C,
                       int M, int K, int N)
{
    gemm64_body(A, B, bias, C, M, K, N, blockIdx.y * 64, blockIdx.x * 64);
}

// both per-type input FCs in one launch (grid.z = type)
__global__ void fc_fused(const float* __restrict__ f0, const float* __restrict__ f1,
                         const float* __restrict__ w0, const float* __restrict__ w1,
                         const float* __restrict__ b0, const float* __restrict__ b1,
                         float* __restrict__ C)
{
    int z = blockIdx.z;
    const float* A = z ? f1 : f0;
    const float* B = z ? w1 : w0;
    const float* bias = z ? b1 : b0;
    float* Cp = z ? C + (size_t)NTYPE0 * 64 : C;
    int M = z ? (NTOT - NTYPE0) : NTYPE0;
    int rowBase = blockIdx.y * 64;
    if (rowBase >= M) return;
    gemm64_body(A, B, bias, Cp, M, 128, 64, rowBase, 0);
}

// ---------------- 128x128 tile fp32 GEMM (R4 shape) + fused attention scores -------
__global__ void __launch_bounds__(256, 2)
gemm128s(const float* __restrict__ A, const float* __restrict__ B,
         float* __restrict__ C, int M, int K, int N,
         long long bStride, long long cStride,
         const float* __restrict__ al, const float* __restrict__ ar,
         float* __restrict__ elb, float* __restrict__ erb)
{
    __shared__ float As[8][132];
    __shared__ float Bs[8][128];
    const float* Bp = B + (long long)blockIdx.z * bStride;
    float* Cp = C + (long long)blockIdx.z * cStride;

    int tid = threadIdx.x;
    int rb = blockIdx.y * 128, cb = blockIdx.x * 128;
    int tx = tid & 15, ty = tid >> 4;
    int arow = tid >> 1, acol = (tid & 1) << 2;
    int brow = tid >> 5, bcol = (tid & 31) << 2;

    unsigned long long acc[8][4];
#pragma unroll
    for (int i = 0; i < 8; i++)
#pragma unroll
        for (int j = 0; j < 4; j++) acc[i][j] = 0ull;

    for (int k0 = 0; k0 < K; k0 += 8) {
        float4 av = make_float4(0.f, 0.f, 0.f, 0.f);
        if (rb + arow < M)
            av = *reinterpret_cast<const float4*>(A + (size_t)(rb + arow) * K + k0 + acol);
        As[acol + 0][arow] = av.x; As[acol + 1][arow] = av.y;
        As[acol + 2][arow] = av.z; As[acol + 3][arow] = av.w;
        float4 bv = *reinterpret_cast<const float4*>(Bp + (size_t)(k0 + brow) * N + cb + bcol);
        *reinterpret_cast<float4*>(&Bs[brow][bcol]) = bv;
        __syncthreads();
#pragma unroll
        for (int k = 0; k < 8; k++) {
            float a[8];
            *reinterpret_cast<float4*>(a)     = *reinterpret_cast<float4*>(&As[k][ty * 8]);
            *reinterpret_cast<float4*>(a + 4) = *reinterpret_cast<float4*>(&As[k][ty * 8 + 4]);
            unsigned long long b2[4];
            b2[0] = *reinterpret_cast<const unsigned long long*>(&Bs[k][tx * 4]);
            b2[1] = *reinterpret_cast<const unsigned long long*>(&Bs[k][tx * 4 + 2]);
            b2[2] = *reinterpret_cast<const unsigned long long*>(&Bs[k][64 + tx * 4]);
            b2[3] = *reinterpret_cast<const unsigned long long*>(&Bs[k][64 + tx * 4 + 2]);
#pragma unroll
            for (int i = 0; i < 8; i++) {
                unsigned long long aa = pack2(a[i], a[i]);
                ffma2(acc[i][0], aa, b2[0]);
                ffma2(acc[i][1], aa, b2[1]);
                ffma2(acc[i][2], aa, b2[2]);
                ffma2(acc[i][3], aa, b2[3]);
            }
        }
        __syncthreads();
    }

    const float* alg = al + (size_t)blockIdx.z * 256;
    const float* arg = ar + (size_t)blockIdx.z * 256;
    float* elg = elb + (size_t)blockIdx.z * (NTOT * 4);
    float* erg = erb + (size_t)blockIdx.z * (NTOT * 4);
    int hbase = cb >> 6;
    float alv0[4], arv0[4], alv1[4], arv1[4];
#pragma unroll
    for (int j = 0; j < 4; j++) {
        alv0[j] = alg[cb + tx * 4 + j];       arv0[j] = arg[cb + tx * 4 + j];
        alv1[j] = alg[cb + 64 + tx * 4 + j];  arv1[j] = arg[cb + 64 + tx * 4 + j];
    }

#pragma unroll
    for (int i = 0; i < 8; i++) {
        int r = rb + ty * 8 + i;
        float2 u0 = unpack2(acc[i][0]), u1 = unpack2(acc[i][1]);
        float2 u2 = unpack2(acc[i][2]), u3 = unpack2(acc[i][3]);
        float v[8] = {u0.x, u0.y, u1.x, u1.y, u2.x, u2.y, u3.x, u3.y};
        *reinterpret_cast<float4*>(Cp + (size_t)r * N + cb + tx * 4)      = *reinterpret_cast<float4*>(v);
        *reinterpret_cast<float4*>(Cp + (size_t)r * N + cb + 64 + tx * 4) = *reinterpret_cast<float4*>(v + 4);

        float se0 = 0.f, sr0 = 0.f, se1 = 0.f, sr1 = 0.f;
#pragma unroll
        for (int j = 0; j < 4; j++) {
            se0 += v[j] * alv0[j];     sr0 += v[j] * arv0[j];
            se1 += v[4 + j] * alv1[j]; sr1 += v[4 + j] * arv1[j];
        }
#pragma unroll
        for (int o = 8; o > 0; o >>= 1) {
            se0 += __shfl_down_sync(~0u, se0, o, 16);
            sr0 += __shfl_down_sync(~0u, sr0, o, 16);
            se1 += __shfl_down_sync(~0u, se1, o, 16);
            sr1 += __shfl_down_sync(~0u, sr1, o, 16);
        }
        if (tx == 0 && r < NTOT) {
            elg[r * 4 + hbase]     = se0;
            erg[r * 4 + hbase]     = sr0;
            elg[r * 4 + hbase + 1] = se1;
            erg[r * 4 + hbase + 1] = sr1;
        }
    }
}

// ---------------- pack layer-2 weights ----------------
__global__ void pack_w2_k(const float* __restrict__ W2, const float* __restrict__ res2,
                          float* __restrict__ out)
{
    int idx = blockIdx.x * blockDim.x + threadIdx.x;
    if (idx >= 256 * 64) return;
    int k = idx >> 6, d = idx & 63;
    int g = (d >> 4) & 1;
    int which = d >> 5;
    int dd = d & 15;
    const float* src = which == 0 ? W2 : res2;
    out[idx] = src[(size_t)g * 256 * 16 + k * 16 + dd];
}

// ---------------- attention scores (layer 2 only): warp per (node, head) -----------
__global__ void scores_k(const float* __restrict__ feat, int stride,
                         const float* __restrict__ al, const float* __restrict__ ar,
                         float* __restrict__ el, float* __restrict__ er, int H, int D)
{
    int n = blockIdx.x;
    int wid = threadIdx.x >> 5;
    int lane = threadIdx.x & 31;
    const float* f = feat + (size_t)n * stride + wid * D;
    float sl = 0.f, sr = 0.f;
    for (int d = lane; d < D; d += 32) {
        float v = f[d];
        sl += v * al[wid * D + d];
        sr += v * ar[wid * D + d];
    }
#pragma unroll
    for (int o = 16; o > 0; o >>= 1) {
        sl += __shfl_down_sync(~0u, sl, o);
        sr += __shfl_down_sync(~0u, sr, o);
    }
    if (lane == 0) { el[n * H + wid] = sl; er[n * H + wid] = sr; }
}

// ---------------- edge softmax (CSR, warp per dst node) — R4 exact form ------------
template <int H>
__global__ void softmax_k(const int* __restrict__ rowptr, const int* __restrict__ csrsrc,
                          const float* __restrict__ el, const float* __restrict__ er,
                          float* __restrict__ alpha)
{
    int n = blockIdx.x * (blockDim.x >> 5) + (threadIdx.x >> 5);
    int lane = threadIdx.x & 31;
    if (n >= NTOT) return;
    int beg = rowptr[n], end = rowptr[n + 1];
    if (beg == end) return;

    float erh[H];
#pragma unroll
    for (int h = 0; h < H; h++) erh[h] = er[n * H + h];

    float mx[H];
#pragma unroll
    for (int h = 0; h < H; h++) mx[h] = -1e30f;

    for (int p = beg + lane; p < end; p += 32) {
        int s = csrsrc[p];
#pragma unroll
        for (int h = 0; h < H; h++) {
            float e = el[s * H + h] + erh[h];
            e = e > 0.f ? e : 0.2f * e;
            alpha[p * H + h] = e;
            mx[h] = fmaxf(mx[h], e);
        }
    }
#pragma unroll
    for (int h = 0; h < H; h++)
#pragma unroll
        for (int o = 16; o > 0; o >>= 1)
            mx[h] = fmaxf(mx[h], __shfl_xor_sync(~0u, mx[h], o));

    float den[H];
#pragma unroll
    for (int h = 0; h < H; h++) den[h] = 0.f;
    for (int p = beg + lane; p < end; p += 32) {
#pragma unroll
        for (int h = 0; h < H; h++) {
            float x = expf(alpha[p * H + h] - mx[h]);
            alpha[p * H + h] = x;
            den[h] += x;
        }
    }
#pragma unroll
    for (int h = 0; h < H; h++)
#pragma unroll
        for (int o = 16; o > 0; o >>= 1)
            den[h] += __shfl_xor_sync(~0u, den[h], o);

    float inv[H];
#pragma unroll
    for (int h = 0; h < H; h++) inv[h] = 1.f / den[h];
    for (int p = beg + lane; p < end; p += 32) {
#pragma unroll
        for (int h = 0; h < H; h++) alpha[p * H + h] *= inv[h];
    }
}

// ---------------- fused dual-graph aggregation + epilogue (HD=256), x4 unroll ------
__global__ void aggr256_k(const int* __restrict__ rp0, const int* __restrict__ cs0,
                          const float* __restrict__ a0, const float* __restrict__ f0,
                          const int* __restrict__ rp1, const int* __restrict__ cs1,
                          const float* __restrict__ a1, const float* __restrict__ f1,
                          const float* __restrict__ h, const float* __restrict__ bias0,
                          const float* __restrict__ bias1, const float* __restrict__ mixw,
                          int layer, int useRes, float* __restrict__ out)
{
    int n = blockIdx.x;
    int d = threadIdx.x;
    int head = d >> 6;

    float acc0 = 0.f, acc1 = 0.f;
    {
        int p = rp0[n], e = rp0[n + 1];
        for (; p + 4 <= e; p += 4) {
            int s0 = __ldg(&cs0[p]),     s1 = __ldg(&cs0[p + 1]);
            int s2 = __ldg(&cs0[p + 2]), s3 = __ldg(&cs0[p + 3]);
            float w0 = __ldg(&a0[(p + 0) * 4 + head]);
            float w1 = __ldg(&a0[(p + 1) * 4 + head]);
            float w2 = __ldg(&a0[(p + 2) * 4 + head]);
            float w3 = __ldg(&a0[(p + 3) * 4 + head]);
            float v0 = f0[(size_t)s0 * 256 + d];
            float v1 = f0[(size_t)s1 * 256 + d];
            float v2 = f0[(size_t)s2 * 256 + d];
            float v3 = f0[(size_t)s3 * 256 + d];
            acc0 += v0 * w0 + v1 * w1 + v2 * w2 + v3 * w3;
        }
        for (; p < e; p++) {
            int s = __ldg(&cs0[p]);
            acc0 += f0[(size_t)s * 256 + d] * __ldg(&a0[p * 4 + head]);
        }
    }
    {
        int p = rp1[n], e = rp1[n + 1];
        for (; p + 4 <= e; p += 4) {
            int s0 = __ldg(&cs1[p]),     s1 = __ldg(&cs1[p + 1]);
            int s2 = __ldg(&cs1[p + 2]), s3 = __ldg(&cs1[p + 3]);
            float w0 = __ldg(&a1[(p + 0) * 4 + head]);
            float w1 = __ldg(&a1[(p + 1) * 4 + head]);
            float w2 = __ldg(&a1[(p + 2) * 4 + head]);
            float w3 = __ldg(&a1[(p + 3) * 4 + head]);
            float v0 = f1[(size_t)s0 * 256 + d];
            float v1 = f1[(size_t)s1 * 256 + d];
            float v2 = f1[(size_t)s2 * 256 + d];
            float v3 = f1[(size_t)s3 * 256 + d];
            acc1 += v0 * w0 + v1 * w1 + v2 * w2 + v3 * w3;
        }
        for (; p < e; p++) {
            int s = __ldg(&cs1[p]);
            acc1 += f1[(size_t)s * 256 + d] * __ldg(&a1[p * 4 + head]);
        }
    }

    float res = useRes ? h[(size_t)n * 256 + d] : 0.f;
    float v0 = acc0 + res + bias0[d];
    float v1 = acc1 + res + bias1[d];
    v0 = v0 > 0.f ? v0 : expm1f(v0);
    v1 = v1 > 0.f ? v1 : expm1f(v1);

    int ty = (n < NTYPE0) ? 0 : 1;
    float m0 = mixw[ty * 6 + layer * 2 + 0];
    float m1 = mixw[ty * 6 + layer * 2 + 1];
    float mxw = fmaxf(m0, m1);
    float e0 = expf(m0 - mxw), e1 = expf(m1 - mxw);
    float inv = 1.f / (e0 + e1);
    out[(size_t)n * 256 + d] = v0 * (e0 * inv) + v1 * (e1 * inv);
}

// ---------------- layer 2 aggregation (H=1, D=16), packed l2 buffer — R4 exact -----
__global__ void aggr16_k(const int* __restrict__ rp0, const int* __restrict__ cs0,
                         const float* __restrict__ a0,
                         const int* __restrict__ rp1, const int* __restrict__ cs1,
                         const float* __restrict__ a1,
                         const float* __restrict__ l2, const float* __restrict__ b2,
                         const float* __restrict__ mixw, float* __restrict__ logits)
{
    int n = blockIdx.x * 16 + (threadIdx.x >> 4);
    int d = threadIdx.x & 15;
    if (n >= NTOT) return;

    float acc0 = 0.f, acc1 = 0.f;
    int b = rp0[n], e = rp0[n + 1];
    for (int p = b; p < e; p++)
        acc0 += l2[(size_t)__ldg(&cs0[p]) * 64 + d] * __ldg(&a0[p]);
    b = rp1[n]; e = rp1[n + 1];
    for (int p = b; p < e; p++)
        acc1 += l2[(size_t)__ldg(&cs1[p]) * 64 + 16 + d] * __ldg(&a1[p]);

    float v0 = acc0 + l2[(size_t)n * 64 + 32 + d] + b2[d];
    float v1 = acc1 + l2[(size_t)n * 64 + 48 + d] + b2[16 + d];

    int ty = (n < NTYPE0) ? 0 : 1;
    float m0 = mixw[ty * 6 + 4 + 0];
    float m1 = mixw[ty * 6 + 4 + 1];
    float mxw = fmaxf(m0, m1);
    float e0 = expf(m0 - mxw), e1 = expf(m1 - mxw);
    float inv = 1.f / (e0 + e1);
    logits[(size_t)n * 16 + d] = v0 * (e0 * inv) + v1 * (e1 * inv);
}

// ---------------- host orchestration (tri-stream fork/join) ----------------
extern "C" void kernel_launch(void* const* d_in, const int* in_sizes, int n_in,
                              void* d_out, int out_size)
{
    const float* features0 = (const float*)d_in[0];
    const float* features1 = (const float*)d_in[1];
    const float* fc_w0 = (const float*)d_in[2];
    const float* fc_b0 = (const float*)d_in[3];
    const float* fc_w1 = (const float*)d_in[4];
    const float* fc_b1 = (const float*)d_in[5];
    const float* mix_w = (const float*)d_in[6];
    const float* W0  = (const float*)d_in[7];
    const float* al0 = (const float*)d_in[8];
    const float* ar0 = (const float*)d_in[9];
    const float* b0  = (const float*)d_in[10];
    const float* W1  = (const float*)d_in[11];
    const float* al1 = (const float*)d_in[12];
    const float* ar1 = (const float*)d_in[13];
    const float* b1  = (const float*)d_in[14];
    const float* W2  = (const float*)d_in[15];
    const float* al2 = (const float*)d_in[16];
    const float* ar2 = (const float*)d_in[17];
    const float* b2  = (const float*)d_in[18];
    const float* res2= (const float*)d_in[19];
    const int* srcs[2] = {(const int*)d_in[20], (const int*)d_in[22]};
    const int* dsts[2] = {(const int*)d_in[21], (const int*)d_in[23]};

    float *h, *acc, *featb, *l2out, *w2pack, *elp, *erp, *alphap;
    int *rowptrp, *cursorp, *countsp, *bsumsp, *csrsrcp;
    cudaGetSymbolAddress((void**)&h,      g_h);
    cudaGetSymbolAddress((void**)&acc,    g_acc);
    cudaGetSymbolAddress((void**)&featb,  g_feat);
    cudaGetSymbolAddress((void**)&l2out,  g_l2out);
    cudaGetSymbolAddress((void**)&w2pack, g_w2pack);
    cudaGetSymbolAddress((void**)&elp,    g_el);
    cudaGetSymbolAddress((void**)&erp,    g_er);
    cudaGetSymbolAddress((void**)&alphap, g_alpha);
    cudaGetSymbolAddress((void**)&rowptrp, g_rowptr);
    cudaGetSymbolAddress((void**)&cursorp, g_cursor);
    cudaGetSymbolAddress((void**)&countsp, g_counts);
    cudaGetSymbolAddress((void**)&bsumsp,  g_bsums);
    cudaGetSymbolAddress((void**)&csrsrcp, g_csrsrc);

    float* feat[2]  = {featb, featb + (size_t)NPAD * 256};
    float* el[2]    = {elp, elp + NTOT * 4};
    float* er[2]    = {erp, erp + NTOT * 4};
    float* alpha[2] = {alphap, alphap + ETOT * 4};
    int* rowptr[2]  = {rowptrp, rowptrp + NTOT + 1};
    int* cursor[2]  = {cursorp, cursorp + NTOT};
    int* counts[2]  = {countsp, countsp + NTOT};
    int* bsums[2]   = {bsumsp, bsumsp + SCAN_NB + 1};
    int* csrsrc[2]  = {csrsrcp, csrsrcp + ETOT};

    const int TPB = 256;
    const int EB = (ETOT + TPB - 1) / TPB;
    const int MB = (NTOT + 127) / 128;
    const int NB = (NTOT + TPB - 1) / TPB;

    static cudaStream_t s2 = nullptr, s3 = nullptr;
    static cudaEvent_t evFork = nullptr, evCsr = nullptr, evCsr3 = nullptr;
    static cudaEvent_t evScore = nullptr, evJoin = nullptr;
    if (s2 == nullptr) {
        cudaStreamCreateWithFlags(&s2, cudaStreamNonBlocking);
        cudaStreamCreateWithFlags(&s3, cudaStreamNonBlocking);
        cudaEventCreateWithFlags(&evFork,  cudaEventDisableTiming);
        cudaEventCreateWithFlags(&evCsr,   cudaEventDisableTiming);
        cudaEventCreateWithFlags(&evCsr3,  cudaEventDisableTiming);
        cudaEventCreateWithFlags(&evScore, cudaEventDisableTiming);
        cudaEventCreateWithFlags(&evJoin,  cudaEventDisableTiming);
    }
    cudaStream_t s0 = 0;

    // ---- fork: graph-0 CSR on s2, graph-1 CSR on s3, FC/projection on s0 ----
    cudaEventRecord(evFork, s0);
    cudaStreamWaitEvent(s2, evFork, 0);
    cudaStreamWaitEvent(s3, evFork, 0);

    zero_k<<<NB, TPB, 0, s2>>>(counts[0], NTOT);
    count_k<<<EB, TPB, 0, s2>>>(dsts[0], counts[0]);
    scanA_k<<<SCAN_NB, SCAN_B, 0, s2>>>(counts[0], cursor[0], bsums[0]);
    scanB_k<<<1, 256, 0, s2>>>(bsums[0]);
    scanC_k<<<SCAN_NB, SCAN_B, 0, s2>>>(cursor[0], bsums[0], rowptr[0], cursor[0]);
    scatter_k<<<EB, TPB, 0, s2>>>(srcs[0], dsts[0], cursor[0], csrsrc[0]);
    pack_w2_k<<<64, 256, 0, s2>>>(W2, res2, w2pack);
    cudaEventRecord(evCsr, s2);

    zero_k<<<NB, TPB, 0, s3>>>(counts[1], NTOT);
    count_k<<<EB, TPB, 0, s3>>>(dsts[1], counts[1]);
    scanA_k<<<SCAN_NB, SCAN_B, 0, s3>>>(counts[1], cursor[1], bsums[1]);
    scanB_k<<<1, 256, 0, s3>>>(bsums[1]);
    scanC_k<<<SCAN_NB, SCAN_B, 0, s3>>>(cursor[1], bsums[1], rowptr[1], cursor[1]);
    scatter_k<<<EB, TPB, 0, s3>>>(srcs[1], dsts[1], cursor[1], csrsrc[1]);
    cudaEventRecord(evCsr3, s3);

    // main chain (s0): fused FCs -> fused projection+scores for layer 0
    fc_fused<<<dim3(1, (NTYPE0 + 63) / 64, 2), TPB, 0, s0>>>(features0, features1,
                                                             fc_w0, fc_w1, fc_b0, fc_b1, h);
    gemm128s<<<dim3(2, MB, 2), 256, 0, s0>>>(h, W0, featb, NTOT, 64, 256,
                                             (long long)64 * 256, (long long)NPAD * 256,
                                             al0, ar0, elp, erp);

    cudaStreamWaitEvent(s0, evCsr, 0);
    cudaStreamWaitEvent(s0, evCsr3, 0);
    cudaStreamWaitEvent(s2, evCsr3, 0);

    float* cur = h;
    float* nxt = acc;
    for (int l = 0; l < 2; l++) {
        const float* bl = (l == 0) ? b0 : b1;
        if (l != 0)
            gemm128s<<<dim3(2, MB, 2), 256, 0, s0>>>(cur, W1, featb, NTOT, 256, 256,
                                                     (long long)256 * 256,
                                                     (long long)NPAD * 256,
                                                     al1, ar1, elp, erp);

        cudaEventRecord(evScore, s0);
        cudaStreamWaitEvent(s2, evScore, 0);
        softmax_k<4><<<(NTOT + 7) / 8, 256, 0, s0>>>(rowptr[0], csrsrc[0], el[0], er[0], alpha[0]);
        softmax_k<4><<<(NTOT + 7) / 8, 256, 0, s2>>>(rowptr[1], csrsrc[1], el[1], er[1], alpha[1]);
        cudaEventRecord(evJoin, s2);
        cudaStreamWaitEvent(s0, evJoin, 0);

        aggr256_k<<<NTOT, 256, 0, s0>>>(rowptr[0], csrsrc[0], alpha[0], feat[0],
                                        rowptr[1], csrsrc[1], alpha[1], feat[1],
                                        cur, bl, bl + 256, mix_w, l, (l == 1) ? 1 : 0, nxt);
        float* t = cur; cur = nxt; nxt = t;
    }

    // ---- layer 2 (H=1, D=16): single packed N=64 GEMM, scores, softmax, aggregate --
    gemm64<<<dim3(1, (NTOT + 63) / 64), TPB, 0, s0>>>(cur, w2pack, nullptr, l2out, NTOT, 256, 64);

    cudaEventRecord(evScore, s0);
    cudaStreamWaitEvent(s2, evScore, 0);
    scores_k<<<NTOT, 32, 0, s0>>>(l2out, 64, al2, ar2, el[0], er[0], 1, 16);
    softmax_k<1><<<(NTOT + 7) / 8, 256, 0, s0>>>(rowptr[0], csrsrc[0], el[0], er[0], alpha[0]);
    scores_k<<<NTOT, 32, 0, s2>>>(l2out + 16, 64, al2 + 16, ar2 + 16, el[1], er[1], 1, 16);
    softmax_k<1><<<(NTOT + 7) / 8, 256, 0, s2>>>(rowptr[1], csrsrc[1], el[1], er[1], alpha[1]);
    cudaEventRecord(evJoin, s2);
    cudaStreamWaitEvent(s0, evJoin, 0);

    aggr16_k<<<(NTOT + 15) / 16, 256, 0, s0>>>(rowptr[0], csrsrc[0], alpha[0],
                                               rowptr[1], csrsrc[1], alpha[1],
                                               l2out, b2, mix_w, (float*)d_out);
}